// round 1
// baseline (speedup 1.0000x reference)
#include <cuda_runtime.h>
#include <cuda_bf16.h>
#include <cstdint>
#include <cstddef>

// ---------------------------------------------------------------------------
// Problem constants
// ---------------------------------------------------------------------------
#define BSZ 2
#define NP  128
#define DIM 1024
#define GEO 64
#define TOPK 18
#define MBIG (BSZ * NP * NP)     // 32768 pairwise rows
#define MSMALL (BSZ * NP)        // 256 proposal rows

// ---------------------------------------------------------------------------
// Scratch (static device globals: allocation-free at kernel_launch time)
// ---------------------------------------------------------------------------
__device__ float g_G3[MBIG * GEO];          // geo MLP output        (8 MB)
__device__ float g_HA[(size_t)MBIG * DIM];  // pairwise act ping     (128 MB)
__device__ float g_HB[(size_t)MBIG * DIM];  // pairwise act pong     (128 MB)
__device__ float g_FA[MSMALL * DIM];        // feats @ pm_w1[0:1024]
__device__ float g_FB[MSMALL * DIM];        // feats @ pm_w1[1024:2048]
__device__ float g_T[MSMALL * DIM];         // topk-summed features
__device__ float g_CAT[MSMALL * 2 * DIM];   // concat(feats, T)
__device__ float g_SA[MSMALL * DIM];        // aggregate ping
__device__ float g_SB[MSMALL * DIM];        // aggregate pong

// ---------------------------------------------------------------------------
// SGEMM: C[M,N] = act( A[M,K] @ B[K,N] + bias + optional pair-add )
// pair-add epilogue (addJ != nullptr): row m = ((b*NP+i)*NP+j)
//   adds addJ[(b*NP+j)*DIM + n] + addI[(b*NP+i)*DIM + n]   (both N==DIM wide)
// Requires M%128==0, N%128==0, K%16==0 (true for all call sites).
// ---------------------------------------------------------------------------
#define BM 128
#define BN 128
#define BK 16

__global__ __launch_bounds__(256, 2)
void sgemm_kernel(const float* __restrict__ A, const float* __restrict__ B,
                  const float* __restrict__ bias, float* __restrict__ C,
                  int M, int N, int K, int relu,
                  const float* __restrict__ addJ, const float* __restrict__ addI)
{
    __shared__ float As[BK][BM + 4];
    __shared__ float Bs[BK][BN];

    const int bm = blockIdx.y * BM;
    const int bn = blockIdx.x * BN;
    const int tid = threadIdx.x;
    const int tx = tid & 15;        // 0..15 -> N micro tile
    const int ty = tid >> 4;        // 0..15 -> M micro tile
    const int arow = tid >> 2;      // 0..63
    const int acol = (tid & 3) << 2;
    const int brow = tid >> 5;      // 0..7
    const int bcol = (tid & 31) << 2;

    float acc[8][8];
#pragma unroll
    for (int a = 0; a < 8; a++)
#pragma unroll
        for (int b = 0; b < 8; b++) acc[a][b] = 0.f;

    const float* Aptr = A + (size_t)(bm + arow) * K + acol;
    const float* Bptr = B + (size_t)brow * N + bn + bcol;

    for (int k0 = 0; k0 < K; k0 += BK) {
        float4 a0 = *(const float4*)(Aptr + k0);
        float4 a1 = *(const float4*)(Aptr + (size_t)64 * K + k0);
        float4 b0 = *(const float4*)(Bptr + (size_t)k0 * N);
        float4 b1 = *(const float4*)(Bptr + (size_t)(k0 + 8) * N);

        __syncthreads();
        As[acol + 0][arow] = a0.x; As[acol + 1][arow] = a0.y;
        As[acol + 2][arow] = a0.z; As[acol + 3][arow] = a0.w;
        As[acol + 0][arow + 64] = a1.x; As[acol + 1][arow + 64] = a1.y;
        As[acol + 2][arow + 64] = a1.z; As[acol + 3][arow + 64] = a1.w;
        *(float4*)&Bs[brow][bcol] = b0;
        *(float4*)&Bs[brow + 8][bcol] = b1;
        __syncthreads();

#pragma unroll
        for (int kk = 0; kk < BK; kk++) {
            float ra[8], rb[8];
#pragma unroll
            for (int a = 0; a < 8; a++) ra[a] = As[kk][ty * 8 + a];
#pragma unroll
            for (int b = 0; b < 8; b++) rb[b] = Bs[kk][tx * 8 + b];
#pragma unroll
            for (int a = 0; a < 8; a++)
#pragma unroll
                for (int b = 0; b < 8; b++)
                    acc[a][b] = fmaf(ra[a], rb[b], acc[a][b]);
        }
    }

    // epilogue
#pragma unroll
    for (int a = 0; a < 8; a++) {
        int m = bm + ty * 8 + a;
        const float* aJ = nullptr;
        const float* aI = nullptr;
        if (addJ) {
            int j = m & (NP - 1);
            int bi = m >> 7;           // b*NP + i
            int bb = bi >> 7;          // b
            aJ = addJ + (size_t)((bb << 7) + j) * DIM;
            aI = addI + (size_t)bi * DIM;
        }
#pragma unroll
        for (int b = 0; b < 8; b++) {
            int n = bn + tx * 8 + b;
            float v = acc[a][b];
            if (bias) v += bias[n];
            if (addJ) v += aJ[n] + aI[n];
            if (relu) v = fmaxf(v, 0.f);
            C[(size_t)m * N + n] = v;
        }
    }
}

// ---------------------------------------------------------------------------
// Geo embedding + 3-layer 64-wide MLP, fused. One thread per (b,i,j) row.
// Per-thread activations live in padded shared memory (dynamic indexing).
// ---------------------------------------------------------------------------
__global__ __launch_bounds__(128)
void geo_kernel(const float* __restrict__ prop,
                const float* __restrict__ w1, const float* __restrict__ b1,
                const float* __restrict__ w2, const float* __restrict__ b2,
                const float* __restrict__ w3, const float* __restrict__ b3,
                float* __restrict__ G3)
{
    __shared__ float sw1[GEO * GEO], sw2[GEO * GEO], sw3[GEO * GEO];
    __shared__ float sb1[GEO], sb2[GEO], sb3[GEO];
    __shared__ float esm[128 * 65];   // per-thread activation buffer, padded

    const int tid = threadIdx.x;
    for (int t = tid; t < GEO * GEO; t += blockDim.x) {
        sw1[t] = w1[t]; sw2[t] = w2[t]; sw3[t] = w3[t];
    }
    for (int t = tid; t < GEO; t += blockDim.x) {
        sb1[t] = b1[t]; sb2[t] = b2[t]; sb3[t] = b3[t];
    }
    __syncthreads();

    const int row = blockIdx.x * blockDim.x + tid;   // 0..32767
    const int b = row >> 14;
    const int i = (row >> 7) & (NP - 1);
    const int j = row & (NP - 1);

    const float* pi = prop + ((size_t)(b * NP + i)) * 4;
    const float* pj = prop + ((size_t)(b * NP + j)) * 4;
    float wi = pi[2] - pi[0] + 1.f, hi = pi[3] - pi[1] + 1.f;
    float wj = pj[2] - pj[0] + 1.f, hj = pj[3] - pj[1] + 1.f;
    float cxi = 0.5f * (pi[0] + pi[2]), cyi = 0.5f * (pi[1] + pi[3]);
    float cxj = 0.5f * (pj[0] + pj[2]), cyj = 0.5f * (pj[1] + pj[3]);

    float pos[4];
    pos[0] = (cxi - cxj) / wj;
    pos[1] = (cyi - cyj) / hj;
    pos[2] = wi / wj;
    pos[3] = hi / hj;

    const float dm[8] = {1.0f, 2.3713737f, 5.6234133f, 13.335215f,
                         31.622777f, 74.989421f, 177.82794f, 421.69650f};

    float* my = &esm[tid * 65];
#pragma unroll
    for (int p = 0; p < 4; p++) {
        float lp = logf(fmaxf(fabsf(pos[p]), 1e-3f)) * 100.f;
#pragma unroll
        for (int r = 0; r < 8; r++) {
            float arg = lp / dm[r];
            float s, c;
            sincosf(arg, &s, &c);
            my[p * 16 + r] = s;
            my[p * 16 + 8 + r] = c;
        }
    }

    float acc[GEO];

    // layer 1 (relu)
#pragma unroll
    for (int o = 0; o < GEO; o++) acc[o] = sb1[o];
    for (int k = 0; k < GEO; k++) {
        float ek = my[k];
        const float* wr = &sw1[k * GEO];
#pragma unroll
        for (int o = 0; o < GEO; o++) acc[o] = fmaf(ek, wr[o], acc[o]);
    }
#pragma unroll
    for (int o = 0; o < GEO; o++) my[o] = fmaxf(acc[o], 0.f);

    // layer 2 (relu)
#pragma unroll
    for (int o = 0; o < GEO; o++) acc[o] = sb2[o];
    for (int k = 0; k < GEO; k++) {
        float ek = my[k];
        const float* wr = &sw2[k * GEO];
#pragma unroll
        for (int o = 0; o < GEO; o++) acc[o] = fmaf(ek, wr[o], acc[o]);
    }
#pragma unroll
    for (int o = 0; o < GEO; o++) my[o] = fmaxf(acc[o], 0.f);

    // layer 3 (linear) -> global
#pragma unroll
    for (int o = 0; o < GEO; o++) acc[o] = sb3[o];
    for (int k = 0; k < GEO; k++) {
        float ek = my[k];
        const float* wr = &sw3[k * GEO];
#pragma unroll
        for (int o = 0; o < GEO; o++) acc[o] = fmaf(ek, wr[o], acc[o]);
    }
    float* outp = G3 + (size_t)row * GEO;
#pragma unroll
    for (int o = 0; o < GEO; o++) outp[o] = acc[o];
}

// ---------------------------------------------------------------------------
// TopK: for each (bi, c), sum top-18 of H[bi*128 + j][c] over j, /8.
// One thread per (bi, c); register-resident sorted list with insertion.
// ---------------------------------------------------------------------------
__global__ __launch_bounds__(256)
void topk_kernel(const float* __restrict__ H, float* __restrict__ T)
{
    int idx = blockIdx.x * blockDim.x + threadIdx.x;    // 0..262143
    int c = idx & (DIM - 1);
    int bi = idx >> 10;                                  // 0..255
    const float* p = H + ((size_t)bi * NP) * DIM + c;

    float t[TOPK];
#pragma unroll
    for (int s = 0; s < TOPK; s++) t[s] = -3.4e38f;

    for (int j = 0; j < NP; j++) {
        float v = p[(size_t)j * DIM];
        if (v > t[TOPK - 1]) {
            t[TOPK - 1] = v;
#pragma unroll
            for (int s = TOPK - 1; s > 0; s--) {
                if (t[s] > t[s - 1]) {
                    float tmp = t[s - 1]; t[s - 1] = t[s]; t[s] = tmp;
                }
            }
        }
    }
    float sum = 0.f;
#pragma unroll
    for (int s = 0; s < TOPK; s++) sum += t[s];
    T[idx] = sum * 0.125f;
}

// ---------------------------------------------------------------------------
// Concat(feats, T) -> CAT [256, 2048]
// ---------------------------------------------------------------------------
__global__ void cat_kernel(const float* __restrict__ feats,
                           const float* __restrict__ T,
                           float* __restrict__ CAT)
{
    int idx = blockIdx.x * blockDim.x + threadIdx.x;  // 0..524287
    int m = idx >> 11;
    int k = idx & 2047;
    float v = (k < DIM) ? feats[(size_t)m * DIM + k]
                        : T[(size_t)m * DIM + (k - DIM)];
    CAT[idx] = v;
}

// ---------------------------------------------------------------------------
// Heads: sigmoid(dot(x, cs_w[:1024]) + dot(sub, cs_w[1024:]) + cs_b), same
// with obj/cso. One block per row.
// ---------------------------------------------------------------------------
__global__ __launch_bounds__(128)
void heads_kernel(const float* __restrict__ X,
                  const float* __restrict__ subject,
                  const float* __restrict__ obj,
                  const float* __restrict__ cs_w, const float* __restrict__ cs_b,
                  const float* __restrict__ cso_w, const float* __restrict__ cso_b,
                  float* __restrict__ out)
{
    int row = blockIdx.x;   // 0..255
    int b = row >> 7;
    int tid = threadIdx.x;

    float as = 0.f, ao = 0.f;
    for (int k = tid; k < DIM; k += 128) {
        float xv = X[(size_t)row * DIM + k];
        float sv = subject[(size_t)b * DIM + k];
        float ov = obj[(size_t)b * DIM + k];
        as += xv * cs_w[k] + sv * cs_w[DIM + k];
        ao += xv * cso_w[k] + ov * cso_w[DIM + k];
    }
    __shared__ float rs[128], ro[128];
    rs[tid] = as; ro[tid] = ao;
    __syncthreads();
    for (int s = 64; s > 0; s >>= 1) {
        if (tid < s) { rs[tid] += rs[tid + s]; ro[tid] += ro[tid + s]; }
        __syncthreads();
    }
    if (tid == 0) {
        float s1 = rs[0] + cs_b[0];
        float s2 = ro[0] + cso_b[0];
        out[row * 2 + 0] = 1.f / (1.f + expf(-s1));
        out[row * 2 + 1] = 1.f / (1.f + expf(-s2));
    }
}

// ---------------------------------------------------------------------------
// Launch
// ---------------------------------------------------------------------------
extern "C" void kernel_launch(void* const* d_in, const int* in_sizes, int n_in,
                              void* d_out, int out_size)
{
    const float* feats   = (const float*)d_in[0];
    const float* subject = (const float*)d_in[1];
    const float* obj     = (const float*)d_in[2];
    const float* prop    = (const float*)d_in[3];
    const float* gp_w1 = (const float*)d_in[4];
    const float* gp_b1 = (const float*)d_in[5];
    const float* gp_w2 = (const float*)d_in[6];
    const float* gp_b2 = (const float*)d_in[7];
    const float* gp_w3 = (const float*)d_in[8];
    const float* gp_b3 = (const float*)d_in[9];
    const float* pm_w1 = (const float*)d_in[10];
    const float* pm_b1 = (const float*)d_in[11];
    const float* pm_w2 = (const float*)d_in[12];
    const float* pm_b2 = (const float*)d_in[13];
    const float* pm_w3 = (const float*)d_in[14];
    const float* pm_b3 = (const float*)d_in[15];
    const float* ag_w1 = (const float*)d_in[16];
    const float* ag_b1 = (const float*)d_in[17];
    const float* ag_w2 = (const float*)d_in[18];
    const float* ag_b2 = (const float*)d_in[19];
    const float* ag_w3 = (const float*)d_in[20];
    const float* ag_b3 = (const float*)d_in[21];
    const float* cs_w  = (const float*)d_in[22];
    const float* cs_b  = (const float*)d_in[23];
    const float* cso_w = (const float*)d_in[24];
    const float* cso_b = (const float*)d_in[25];
    float* out = (float*)d_out;

    float *G3, *HA, *HB, *FA, *FB, *T, *CAT, *SA, *SB;
    cudaGetSymbolAddress((void**)&G3, g_G3);
    cudaGetSymbolAddress((void**)&HA, g_HA);
    cudaGetSymbolAddress((void**)&HB, g_HB);
    cudaGetSymbolAddress((void**)&FA, g_FA);
    cudaGetSymbolAddress((void**)&FB, g_FB);
    cudaGetSymbolAddress((void**)&T,  g_T);
    cudaGetSymbolAddress((void**)&CAT, g_CAT);
    cudaGetSymbolAddress((void**)&SA, g_SA);
    cudaGetSymbolAddress((void**)&SB, g_SB);

    dim3 gsmall(DIM / BN, MSMALL / BM);       // (8, 2)
    dim3 gbig(DIM / BN, MBIG / BM);           // (8, 256)

    // FA = feats @ pm_w1[0:1024,:], FB = feats @ pm_w1[1024:2048,:]
    sgemm_kernel<<<gsmall, 256>>>(feats, pm_w1, nullptr, FA,
                                  MSMALL, DIM, DIM, 0, nullptr, nullptr);
    sgemm_kernel<<<gsmall, 256>>>(feats, pm_w1 + (size_t)DIM * DIM, nullptr, FB,
                                  MSMALL, DIM, DIM, 0, nullptr, nullptr);

    // Geo embedding + geo MLP
    geo_kernel<<<MBIG / 128, 128>>>(prop, gp_w1, gp_b1, gp_w2, gp_b2,
                                    gp_w3, gp_b3, G3);

    // Pairwise layer 1: relu(G3 @ pm_w1[2048:2112,:] + FA_j + FB_i + b1)
    sgemm_kernel<<<gbig, 256>>>(G3, pm_w1 + (size_t)2 * DIM * DIM, pm_b1, HA,
                                MBIG, DIM, GEO, 1, FA, FB);
    // Pairwise layer 2
    sgemm_kernel<<<gbig, 256>>>(HA, pm_w2, pm_b2, HB,
                                MBIG, DIM, DIM, 1, nullptr, nullptr);
    // Pairwise layer 3 (linear)
    sgemm_kernel<<<gbig, 256>>>(HB, pm_w3, pm_b3, HA,
                                MBIG, DIM, DIM, 0, nullptr, nullptr);

    // TopK over j, sum/8
    topk_kernel<<<(MSMALL * DIM) / 256, 256>>>(HA, T);

    // Aggregate MLP
    cat_kernel<<<(MSMALL * 2 * DIM) / 256, 256>>>(feats, T, CAT);
    sgemm_kernel<<<gsmall, 256>>>(CAT, ag_w1, ag_b1, SA,
                                  MSMALL, DIM, 2 * DIM, 1, nullptr, nullptr);
    sgemm_kernel<<<gsmall, 256>>>(SA, ag_w2, ag_b2, SB,
                                  MSMALL, DIM, DIM, 1, nullptr, nullptr);
    sgemm_kernel<<<gsmall, 256>>>(SB, ag_w3, ag_b3, SA,
                                  MSMALL, DIM, DIM, 0, nullptr, nullptr);

    // Heads
    heads_kernel<<<MSMALL, 128>>>(SA, subject, obj, cs_w, cs_b, cso_w, cso_b, out);
}

// round 3
// speedup vs baseline: 1.9597x; 1.9597x over previous
#include <cuda_runtime.h>
#include <cuda_bf16.h>
#include <cstdint>
#include <cstddef>

// ---------------------------------------------------------------------------
// Problem constants
// ---------------------------------------------------------------------------
#define BSZ 2
#define NP  128
#define DIM 1024
#define GEO 64
#define TOPK 18
#define MBIG (BSZ * NP * NP)     // 32768 pairwise rows
#define MSMALL (BSZ * NP)        // 256 proposal rows

// ---------------------------------------------------------------------------
// Scratch (static device globals)
// ---------------------------------------------------------------------------
__device__ float g_G3[MBIG * GEO];
__device__ float g_HA[(size_t)MBIG * DIM];       // layer-3 output fp32 (128 MB)
__device__ float g_FA[MSMALL * DIM];
__device__ float g_FB[MSMALL * DIM];
__device__ float g_T[MSMALL * DIM];
__device__ float g_CAT[MSMALL * 2 * DIM];
__device__ float g_SA[MSMALL * DIM];
__device__ float g_SB[MSMALL * DIM];
__device__ unsigned short g_H1hi[(size_t)MBIG * DIM];  // 64 MB each
__device__ unsigned short g_H1lo[(size_t)MBIG * DIM];
__device__ unsigned short g_H2hi[(size_t)MBIG * DIM];
__device__ unsigned short g_H2lo[(size_t)MBIG * DIM];
__device__ unsigned short g_W2hi[DIM * DIM];     // [N,K] transposed
__device__ unsigned short g_W2lo[DIM * DIM];
__device__ unsigned short g_W3hi[DIM * DIM];
__device__ unsigned short g_W3lo[DIM * DIM];

// ---------------------------------------------------------------------------
// Helpers (sm_80+ only: cp.async, ldmatrix, mma.sync — no tcgen05!)
// ---------------------------------------------------------------------------
__device__ __forceinline__ uint32_t smem_u32(const void* p) {
    uint32_t a;
    asm("{ .reg .u64 t; cvta.to.shared.u64 t, %1; cvt.u32.u64 %0, t; }"
        : "=r"(a) : "l"(p));
    return a;
}
__device__ __forceinline__ void cp16(uint32_t dst, const void* src) {
    asm volatile("cp.async.cg.shared.global [%0], [%1], 16;" :: "r"(dst), "l"(src));
}
__device__ __forceinline__ void cp_commit() {
    asm volatile("cp.async.commit_group;" ::: "memory");
}
template<int N> __device__ __forceinline__ void cp_wait() {
    asm volatile("cp.async.wait_group %0;" :: "n"(N) : "memory");
}
#define SWZ128(o) ((o) ^ (((o) >> 3) & 0x70))

__device__ __forceinline__ void ldsm4(uint32_t& r0, uint32_t& r1,
                                      uint32_t& r2, uint32_t& r3, uint32_t addr) {
    asm volatile("ldmatrix.sync.aligned.m8n8.x4.shared.b16 {%0,%1,%2,%3}, [%4];"
                 : "=r"(r0), "=r"(r1), "=r"(r2), "=r"(r3) : "r"(addr));
}
__device__ __forceinline__ void mma_bf16(float* c,
                                         const uint32_t* a, const uint32_t* b) {
    asm volatile("mma.sync.aligned.m16n8k16.row.col.f32.bf16.bf16.f32 "
                 "{%0,%1,%2,%3}, {%4,%5,%6,%7}, {%8,%9}, {%0,%1,%2,%3};"
                 : "+f"(c[0]), "+f"(c[1]), "+f"(c[2]), "+f"(c[3])
                 : "r"(a[0]), "r"(a[1]), "r"(a[2]), "r"(a[3]),
                   "r"(b[0]), "r"(b[1]));
}

__device__ __forceinline__ unsigned short f2bf_bits(float v) {
    __nv_bfloat16 h = __float2bfloat16(v);
    return *reinterpret_cast<unsigned short*>(&h);
}
__device__ __forceinline__ float bf_bits2f(unsigned short u) {
    __nv_bfloat16 h = *reinterpret_cast<__nv_bfloat16*>(&u);
    return __bfloat162float(h);
}

// ---------------------------------------------------------------------------
// HMMA big GEMM: out = act( A @ B^T + bias ), hi/lo bf16 split, fp32 acc.
// A{hi,lo} [MBIG, DIM] row-major bf16-bits; B{hi,lo} [DIM(N), DIM(K)] row-major.
// CTA tile 128x128; 8 warps as 2(M)x4(N); warp tile 64x32.
// K chunk = 64 bf16 (128B rows, SW128). 2-stage cp.async pipeline.
// Stage layout: Ahi @0, Alo @16K, Bhi @32K, Blo @48K (each 16 KB).
// ---------------------------------------------------------------------------
#define KCH 64
#define NKC (DIM / KCH)            // 16
#define STG_BYTES 65536
#define HMMA_SMEM (2 * STG_BYTES + 128)

__global__ void __launch_bounds__(256, 1)
hmma_kernel(const unsigned short* __restrict__ Ahi,
            const unsigned short* __restrict__ Alo,
            const unsigned short* __restrict__ Bhi,
            const unsigned short* __restrict__ Blo,
            const float* __restrict__ bias, int relu,
            unsigned short* __restrict__ outHi,
            unsigned short* __restrict__ outLo,
            float* __restrict__ outF)
{
    extern __shared__ char smem_raw[];
    const uint32_t sbase = (smem_u32(smem_raw) + 127u) & ~127u;
    const int tid = threadIdx.x;
    const int mtile = blockIdx.y, ntile = blockIdx.x;
    const int lane = tid & 31;
    const int w = tid >> 5;
    const int wm = w >> 2;          // 0..1
    const int wn = w & 3;           // 0..3

    float acc[4][4][4];
#pragma unroll
    for (int mf = 0; mf < 4; mf++)
#pragma unroll
        for (int nf = 0; nf < 4; nf++)
#pragma unroll
            for (int e = 0; e < 4; e++) acc[mf][nf][e] = 0.f;

    const unsigned short* srcs[4] = { Ahi, Alo, Bhi, Blo };

    auto load_chunk = [&](int kc, int stg) {
        const uint32_t s0 = sbase + (uint32_t)stg * STG_BYTES;
#pragma unroll
        for (int t4 = 0; t4 < 4; t4++) {
            const unsigned short* src = srcs[t4];
            const int rowbase = (t4 < 2 ? mtile : ntile) << 7;
            const uint32_t dtile = s0 + t4 * 16384u;
#pragma unroll
            for (int it = 0; it < 4; it++) {
                int t = tid + (it << 8);
                int rr = t >> 3, ss = t & 7;
                cp16(dtile + SWZ128((uint32_t)(rr * 128 + ss * 16)),
                     src + (size_t)(rowbase + rr) * DIM + kc * KCH + ss * 8);
            }
        }
        cp_commit();
    };

    // ldmatrix lane addressing (tile-relative, before swizzle):
    // A 16x16 @ (m0,k0): row = m0 + (lane&15), col = k0 + (lane>>4)*8
    // B 16x16 @ (n0,k0): row = n0 + (lane&7) + ((lane>>4)<<3), col = k0 + ((lane>>3)&1)*8
    const int a_rl = lane & 15;
    const int a_cl = (lane >> 4) << 3;
    const int b_rl = (lane & 7) + ((lane >> 4) << 3);
    const int b_cl = ((lane >> 3) & 1) << 3;

    auto compute = [&](int stg) {
        const uint32_t s0 = sbase + (uint32_t)stg * STG_BYTES;
        const uint32_t sAhi = s0, sAlo = s0 + 16384u;
        const uint32_t sBhi = s0 + 32768u, sBlo = s0 + 49152u;
#pragma unroll
        for (int ks = 0; ks < 4; ks++) {
            const int k0 = ks * 16;
            // B fragments (hi & lo), 4 n-frags via 2 x4-ldmatrix each
            uint32_t bh[4][2], bl[4][2];
#pragma unroll
            for (int np = 0; np < 2; np++) {
                const int n0 = wn * 32 + np * 16;
                const uint32_t off =
                    SWZ128((uint32_t)((n0 + b_rl) * 128 + (k0 + b_cl) * 2));
                uint32_t r0, r1, r2, r3;
                ldsm4(r0, r1, r2, r3, sBhi + off);
                bh[np * 2][0] = r0; bh[np * 2][1] = r1;
                bh[np * 2 + 1][0] = r2; bh[np * 2 + 1][1] = r3;
                ldsm4(r0, r1, r2, r3, sBlo + off);
                bl[np * 2][0] = r0; bl[np * 2][1] = r1;
                bl[np * 2 + 1][0] = r2; bl[np * 2 + 1][1] = r3;
            }
            // A-hi fragments; mma hi*hi + hi*lo
            uint32_t af[4][4];
#pragma unroll
            for (int mf = 0; mf < 4; mf++) {
                const int m0 = wm * 64 + mf * 16;
                const uint32_t off =
                    SWZ128((uint32_t)((m0 + a_rl) * 128 + (k0 + a_cl) * 2));
                ldsm4(af[mf][0], af[mf][1], af[mf][2], af[mf][3], sAhi + off);
            }
#pragma unroll
            for (int mf = 0; mf < 4; mf++)
#pragma unroll
                for (int nf = 0; nf < 4; nf++) {
                    mma_bf16(acc[mf][nf], af[mf], bh[nf]);
                    mma_bf16(acc[mf][nf], af[mf], bl[nf]);
                }
            // A-lo fragments; mma lo*hi
#pragma unroll
            for (int mf = 0; mf < 4; mf++) {
                const int m0 = wm * 64 + mf * 16;
                const uint32_t off =
                    SWZ128((uint32_t)((m0 + a_rl) * 128 + (k0 + a_cl) * 2));
                ldsm4(af[mf][0], af[mf][1], af[mf][2], af[mf][3], sAlo + off);
            }
#pragma unroll
            for (int mf = 0; mf < 4; mf++)
#pragma unroll
                for (int nf = 0; nf < 4; nf++)
                    mma_bf16(acc[mf][nf], af[mf], bh[nf]);
        }
    };

    load_chunk(0, 0);
    for (int kc = 0; kc < NKC; kc++) {
        if (kc + 1 < NKC) {
            load_chunk(kc + 1, (kc + 1) & 1);
            cp_wait<1>();
        } else {
            cp_wait<0>();
        }
        __syncthreads();
        compute(kc & 1);
        __syncthreads();
    }

    // Epilogue: acc[mf][nf] -> (row0+{0,8}, col0+{0,1})
    const int rl = lane >> 2;           // 0..7
    const int cl = (lane & 3) << 1;     // 0,2,4,6
#pragma unroll
    for (int mf = 0; mf < 4; mf++) {
        const int m_base = (mtile << 7) + wm * 64 + mf * 16 + rl;
#pragma unroll
        for (int nf = 0; nf < 4; nf++) {
            const int n = (ntile << 7) + wn * 32 + nf * 8 + cl;
            const float b0 = bias[n], b1 = bias[n + 1];
#pragma unroll
            for (int half = 0; half < 2; half++) {
                const int m = m_base + half * 8;
                float v0 = acc[mf][nf][half * 2 + 0] + b0;
                float v1 = acc[mf][nf][half * 2 + 1] + b1;
                if (relu) { v0 = fmaxf(v0, 0.f); v1 = fmaxf(v1, 0.f); }
                if (outF) {
                    float2 f2; f2.x = v0; f2.y = v1;
                    *(float2*)(outF + (size_t)m * DIM + n) = f2;
                } else {
                    unsigned short h0 = f2bf_bits(v0);
                    unsigned short h1 = f2bf_bits(v1);
                    unsigned short l0 = f2bf_bits(v0 - bf_bits2f(h0));
                    unsigned short l1 = f2bf_bits(v1 - bf_bits2f(h1));
                    *(uint32_t*)(outHi + (size_t)m * DIM + n) =
                        (uint32_t)h0 | ((uint32_t)h1 << 16);
                    *(uint32_t*)(outLo + (size_t)m * DIM + n) =
                        (uint32_t)l0 | ((uint32_t)l1 << 16);
                }
            }
        }
    }
}

// ---------------------------------------------------------------------------
// Weight transpose + bf16 hi/lo split:  W[K,N] -> Whi/Wlo [N,K]
// ---------------------------------------------------------------------------
__global__ void wsplit_kernel(const float* __restrict__ W,
                              unsigned short* __restrict__ Whi,
                              unsigned short* __restrict__ Wlo)
{
    __shared__ float tile[32][33];
    const int n0 = blockIdx.x * 32, k0 = blockIdx.y * 32;
    const int tx = threadIdx.x, ty = threadIdx.y;   // 32 x 8
#pragma unroll
    for (int i = 0; i < 32; i += 8)
        tile[ty + i][tx] = W[(size_t)(k0 + ty + i) * DIM + n0 + tx];
    __syncthreads();
#pragma unroll
    for (int i = 0; i < 32; i += 8) {
        float v = tile[tx][ty + i];
        unsigned short hb = f2bf_bits(v);
        unsigned short lb = f2bf_bits(v - bf_bits2f(hb));
        size_t idx = (size_t)(n0 + ty + i) * DIM + k0 + tx;
        Whi[idx] = hb;
        Wlo[idx] = lb;
    }
}

// ---------------------------------------------------------------------------
// fp32 SGEMM (FA/FB, layer-1, aggregate) + optional pair-add / split output
// ---------------------------------------------------------------------------
#define BM 128
#define BN 128
#define BK 16

__global__ __launch_bounds__(256, 2)
void sgemm_kernel(const float* __restrict__ A, const float* __restrict__ B,
                  const float* __restrict__ bias, float* __restrict__ C,
                  int M, int N, int K, int relu,
                  const float* __restrict__ addJ, const float* __restrict__ addI,
                  unsigned short* __restrict__ outHi,
                  unsigned short* __restrict__ outLo)
{
    __shared__ float As[BK][BM + 4];
    __shared__ float Bs[BK][BN];

    const int bm = blockIdx.y * BM;
    const int bn = blockIdx.x * BN;
    const int tid = threadIdx.x;
    const int tx = tid & 15;
    const int ty = tid >> 4;
    const int arow = tid >> 2;
    const int acol = (tid & 3) << 2;
    const int brow = tid >> 5;
    const int bcol = (tid & 31) << 2;

    float acc[8][8];
#pragma unroll
    for (int a = 0; a < 8; a++)
#pragma unroll
        for (int b = 0; b < 8; b++) acc[a][b] = 0.f;

    const float* Aptr = A + (size_t)(bm + arow) * K + acol;
    const float* Bptr = B + (size_t)brow * N + bn + bcol;

    for (int k0 = 0; k0 < K; k0 += BK) {
        float4 a0 = *(const float4*)(Aptr + k0);
        float4 a1 = *(const float4*)(Aptr + (size_t)64 * K + k0);
        float4 b0 = *(const float4*)(Bptr + (size_t)k0 * N);
        float4 b1 = *(const float4*)(Bptr + (size_t)(k0 + 8) * N);

        __syncthreads();
        As[acol + 0][arow] = a0.x; As[acol + 1][arow] = a0.y;
        As[acol + 2][arow] = a0.z; As[acol + 3][arow] = a0.w;
        As[acol + 0][arow + 64] = a1.x; As[acol + 1][arow + 64] = a1.y;
        As[acol + 2][arow + 64] = a1.z; As[acol + 3][arow + 64] = a1.w;
        *(float4*)&Bs[brow][bcol] = b0;
        *(float4*)&Bs[brow + 8][bcol] = b1;
        __syncthreads();

#pragma unroll
        for (int kk = 0; kk < BK; kk++) {
            float ra[8], rb[8];
#pragma unroll
            for (int a = 0; a < 8; a++) ra[a] = As[kk][ty * 8 + a];
#pragma unroll
            for (int b = 0; b < 8; b++) rb[b] = Bs[kk][tx * 8 + b];
#pragma unroll
            for (int a = 0; a < 8; a++)
#pragma unroll
                for (int b = 0; b < 8; b++)
                    acc[a][b] = fmaf(ra[a], rb[b], acc[a][b]);
        }
    }

#pragma unroll
    for (int a = 0; a < 8; a++) {
        int m = bm + ty * 8 + a;
        const float* aJ = nullptr;
        const float* aI = nullptr;
        if (addJ) {
            int j = m & (NP - 1);
            int bi = m >> 7;
            int bb = bi >> 7;
            aJ = addJ + (size_t)((bb << 7) + j) * DIM;
            aI = addI + (size_t)bi * DIM;
        }
#pragma unroll
        for (int b = 0; b < 8; b += 2) {
            int n = bn + tx * 8 + b;
            float v0 = acc[a][b], v1 = acc[a][b + 1];
            if (bias) { v0 += bias[n]; v1 += bias[n + 1]; }
            if (addJ) { v0 += aJ[n] + aI[n]; v1 += aJ[n + 1] + aI[n + 1]; }
            if (relu) { v0 = fmaxf(v0, 0.f); v1 = fmaxf(v1, 0.f); }
            if (outHi) {
                unsigned short h0 = f2bf_bits(v0), h1 = f2bf_bits(v1);
                unsigned short l0 = f2bf_bits(v0 - bf_bits2f(h0));
                unsigned short l1 = f2bf_bits(v1 - bf_bits2f(h1));
                *(uint32_t*)(outHi + (size_t)m * N + n) =
                    (uint32_t)h0 | ((uint32_t)h1 << 16);
                *(uint32_t*)(outLo + (size_t)m * N + n) =
                    (uint32_t)l0 | ((uint32_t)l1 << 16);
            } else {
                C[(size_t)m * N + n] = v0;
                C[(size_t)m * N + n + 1] = v1;
            }
        }
    }
}

// ---------------------------------------------------------------------------
// Geo embedding + 3-layer 64-wide MLP (fused)
// ---------------------------------------------------------------------------
__global__ __launch_bounds__(128)
void geo_kernel(const float* __restrict__ prop,
                const float* __restrict__ w1, const float* __restrict__ b1,
                const float* __restrict__ w2, const float* __restrict__ b2,
                const float* __restrict__ w3, const float* __restrict__ b3,
                float* __restrict__ G3)
{
    __shared__ float sw1[GEO * GEO], sw2[GEO * GEO], sw3[GEO * GEO];
    __shared__ float sb1[GEO], sb2[GEO], sb3[GEO];
    __shared__ float esm[128 * 65];

    const int tid = threadIdx.x;
    for (int t = tid; t < GEO * GEO; t += blockDim.x) {
        sw1[t] = w1[t]; sw2[t] = w2[t]; sw3[t] = w3[t];
    }
    for (int t = tid; t < GEO; t += blockDim.x) {
        sb1[t] = b1[t]; sb2[t] = b2[t]; sb3[t] = b3[t];
    }
    __syncthreads();

    const int row = blockIdx.x * blockDim.x + tid;
    const int b = row >> 14;
    const int i = (row >> 7) & (NP - 1);
    const int j = row & (NP - 1);

    const float* pi = prop + ((size_t)(b * NP + i)) * 4;
    const float* pj = prop + ((size_t)(b * NP + j)) * 4;
    float wi = pi[2] - pi[0] + 1.f, hi = pi[3] - pi[1] + 1.f;
    float wj = pj[2] - pj[0] + 1.f, hj = pj[3] - pj[1] + 1.f;
    float cxi = 0.5f * (pi[0] + pi[2]), cyi = 0.5f * (pi[1] + pi[3]);
    float cxj = 0.5f * (pj[0] + pj[2]), cyj = 0.5f * (pj[1] + pj[3]);

    float pos[4];
    pos[0] = (cxi - cxj) / wj;
    pos[1] = (cyi - cyj) / hj;
    pos[2] = wi / wj;
    pos[3] = hi / hj;

    const float dm[8] = {1.0f, 2.3713737f, 5.6234133f, 13.335215f,
                         31.622777f, 74.989421f, 177.82794f, 421.69650f};

    float* my = &esm[tid * 65];
#pragma unroll
    for (int p = 0; p < 4; p++) {
        float lp = logf(fmaxf(fabsf(pos[p]), 1e-3f)) * 100.f;
#pragma unroll
        for (int r = 0; r < 8; r++) {
            float arg = lp / dm[r];
            float s, c;
            sincosf(arg, &s, &c);
            my[p * 16 + r] = s;
            my[p * 16 + 8 + r] = c;
        }
    }

    float acc[GEO];
#pragma unroll
    for (int o = 0; o < GEO; o++) acc[o] = sb1[o];
    for (int k = 0; k < GEO; k++) {
        float ek = my[k];
        const float* wr = &sw1[k * GEO];
#pragma unroll
        for (int o = 0; o < GEO; o++) acc[o] = fmaf(ek, wr[o], acc[o]);
    }
#pragma unroll
    for (int o = 0; o < GEO; o++) my[o] = fmaxf(acc[o], 0.f);

#pragma unroll
    for (int o = 0; o < GEO; o++) acc[o] = sb2[o];
    for (int k = 0; k < GEO; k++) {
        float ek = my[k];
        const float* wr = &sw2[k * GEO];
#pragma unroll
        for (int o = 0; o < GEO; o++) acc[o] = fmaf(ek, wr[o], acc[o]);
    }
#pragma unroll
    for (int o = 0; o < GEO; o++) my[o] = fmaxf(acc[o], 0.f);

#pragma unroll
    for (int o = 0; o < GEO; o++) acc[o] = sb3[o];
    for (int k = 0; k < GEO; k++) {
        float ek = my[k];
        const float* wr = &sw3[k * GEO];
#pragma unroll
        for (int o = 0; o < GEO; o++) acc[o] = fmaf(ek, wr[o], acc[o]);
    }
    float* outp = G3 + (size_t)row * GEO;
#pragma unroll
    for (int o = 0; o < GEO; o++) outp[o] = acc[o];
}

// ---------------------------------------------------------------------------
// TopK + concat + heads
// ---------------------------------------------------------------------------
__global__ __launch_bounds__(256)
void topk_kernel(const float* __restrict__ H, float* __restrict__ T)
{
    int idx = blockIdx.x * blockDim.x + threadIdx.x;
    int c = idx & (DIM - 1);
    int bi = idx >> 10;
    const float* p = H + ((size_t)bi * NP) * DIM + c;

    float t[TOPK];
#pragma unroll
    for (int s = 0; s < TOPK; s++) t[s] = -3.4e38f;

    for (int j = 0; j < NP; j++) {
        float v = p[(size_t)j * DIM];
        if (v > t[TOPK - 1]) {
            t[TOPK - 1] = v;
#pragma unroll
            for (int s = TOPK - 1; s > 0; s--) {
                if (t[s] > t[s - 1]) {
                    float tmp = t[s - 1]; t[s - 1] = t[s]; t[s] = tmp;
                }
            }
        }
    }
    float sum = 0.f;
#pragma unroll
    for (int s = 0; s < TOPK; s++) sum += t[s];
    T[idx] = sum * 0.125f;
}

__global__ void cat_kernel(const float* __restrict__ feats,
                           const float* __restrict__ T,
                           float* __restrict__ CAT)
{
    int idx = blockIdx.x * blockDim.x + threadIdx.x;
    int m = idx >> 11;
    int k = idx & 2047;
    float v = (k < DIM) ? feats[(size_t)m * DIM + k]
                        : T[(size_t)m * DIM + (k - DIM)];
    CAT[idx] = v;
}

__global__ __launch_bounds__(128)
void heads_kernel(const float* __restrict__ X,
                  const float* __restrict__ subject,
                  const float* __restrict__ obj,
                  const float* __restrict__ cs_w, const float* __restrict__ cs_b,
                  const float* __restrict__ cso_w, const float* __restrict__ cso_b,
                  float* __restrict__ out)
{
    int row = blockIdx.x;
    int b = row >> 7;
    int tid = threadIdx.x;

    float as = 0.f, ao = 0.f;
    for (int k = tid; k < DIM; k += 128) {
        float xv = X[(size_t)row * DIM + k];
        float sv = subject[(size_t)b * DIM + k];
        float ov = obj[(size_t)b * DIM + k];
        as += xv * cs_w[k] + sv * cs_w[DIM + k];
        ao += xv * cso_w[k] + ov * cso_w[DIM + k];
    }
    __shared__ float rs[128], ro[128];
    rs[tid] = as; ro[tid] = ao;
    __syncthreads();
    for (int s = 64; s > 0; s >>= 1) {
        if (tid < s) { rs[tid] += rs[tid + s]; ro[tid] += ro[tid + s]; }
        __syncthreads();
    }
    if (tid == 0) {
        float s1 = rs[0] + cs_b[0];
        float s2 = ro[0] + cso_b[0];
        out[row * 2 + 0] = 1.f / (1.f + expf(-s1));
        out[row * 2 + 1] = 1.f / (1.f + expf(-s2));
    }
}

// ---------------------------------------------------------------------------
// Launch
// ---------------------------------------------------------------------------
extern "C" void kernel_launch(void* const* d_in, const int* in_sizes, int n_in,
                              void* d_out, int out_size)
{
    const float* feats   = (const float*)d_in[0];
    const float* subject = (const float*)d_in[1];
    const float* obj     = (const float*)d_in[2];
    const float* prop    = (const float*)d_in[3];
    const float* gp_w1 = (const float*)d_in[4];
    const float* gp_b1 = (const float*)d_in[5];
    const float* gp_w2 = (const float*)d_in[6];
    const float* gp_b2 = (const float*)d_in[7];
    const float* gp_w3 = (const float*)d_in[8];
    const float* gp_b3 = (const float*)d_in[9];
    const float* pm_w1 = (const float*)d_in[10];
    const float* pm_b1 = (const float*)d_in[11];
    const float* pm_w2 = (const float*)d_in[12];
    const float* pm_b2 = (const float*)d_in[13];
    const float* pm_w3 = (const float*)d_in[14];
    const float* pm_b3 = (const float*)d_in[15];
    const float* ag_w1 = (const float*)d_in[16];
    const float* ag_b1 = (const float*)d_in[17];
    const float* ag_w2 = (const float*)d_in[18];
    const float* ag_b2 = (const float*)d_in[19];
    const float* ag_w3 = (const float*)d_in[20];
    const float* ag_b3 = (const float*)d_in[21];
    const float* cs_w  = (const float*)d_in[22];
    const float* cs_b  = (const float*)d_in[23];
    const float* cso_w = (const float*)d_in[24];
    const float* cso_b = (const float*)d_in[25];
    float* out = (float*)d_out;

    float *G3, *HA, *FA, *FB, *T, *CAT, *SA, *SB;
    unsigned short *H1hi, *H1lo, *H2hi, *H2lo, *W2hi, *W2lo, *W3hi, *W3lo;
    cudaGetSymbolAddress((void**)&G3, g_G3);
    cudaGetSymbolAddress((void**)&HA, g_HA);
    cudaGetSymbolAddress((void**)&FA, g_FA);
    cudaGetSymbolAddress((void**)&FB, g_FB);
    cudaGetSymbolAddress((void**)&T,  g_T);
    cudaGetSymbolAddress((void**)&CAT, g_CAT);
    cudaGetSymbolAddress((void**)&SA, g_SA);
    cudaGetSymbolAddress((void**)&SB, g_SB);
    cudaGetSymbolAddress((void**)&H1hi, g_H1hi);
    cudaGetSymbolAddress((void**)&H1lo, g_H1lo);
    cudaGetSymbolAddress((void**)&H2hi, g_H2hi);
    cudaGetSymbolAddress((void**)&H2lo, g_H2lo);
    cudaGetSymbolAddress((void**)&W2hi, g_W2hi);
    cudaGetSymbolAddress((void**)&W2lo, g_W2lo);
    cudaGetSymbolAddress((void**)&W3hi, g_W3hi);
    cudaGetSymbolAddress((void**)&W3lo, g_W3lo);

    cudaFuncSetAttribute(hmma_kernel,
                         cudaFuncAttributeMaxDynamicSharedMemorySize, HMMA_SMEM);

    dim3 gsmall(DIM / BN, MSMALL / BM);       // (8, 2)
    dim3 gbig(DIM / BN, MBIG / BM);           // (8, 256)
    dim3 ghm(DIM / 128, MBIG / 128);          // (8, 256)
    dim3 gws(DIM / 32, DIM / 32);

    // Weight transpose + split (tiny)
    wsplit_kernel<<<gws, dim3(32, 8)>>>(pm_w2, W2hi, W2lo);
    wsplit_kernel<<<gws, dim3(32, 8)>>>(pm_w3, W3hi, W3lo);

    // FA/FB precompute
    sgemm_kernel<<<gsmall, 256>>>(feats, pm_w1, nullptr, FA,
                                  MSMALL, DIM, DIM, 0, nullptr, nullptr,
                                  nullptr, nullptr);
    sgemm_kernel<<<gsmall, 256>>>(feats, pm_w1 + (size_t)DIM * DIM, nullptr, FB,
                                  MSMALL, DIM, DIM, 0, nullptr, nullptr,
                                  nullptr, nullptr);

    // Geo embedding + geo MLP
    geo_kernel<<<MBIG / 128, 128>>>(prop, gp_w1, gp_b1, gp_w2, gp_b2,
                                    gp_w3, gp_b3, G3);

    // Pairwise layer 1 (K=64, fp32 SIMT) -> H1 bf16 hi/lo
    sgemm_kernel<<<gbig, 256>>>(G3, pm_w1 + (size_t)2 * DIM * DIM, pm_b1, nullptr,
                                MBIG, DIM, GEO, 1, FA, FB, H1hi, H1lo);

    // Pairwise layer 2 (HMMA, split bf16) -> H2 hi/lo, relu
    hmma_kernel<<<ghm, 256, HMMA_SMEM>>>(H1hi, H1lo, W2hi, W2lo, pm_b2, 1,
                                         H2hi, H2lo, nullptr);
    // Pairwise layer 3 (HMMA) -> HA fp32, linear
    hmma_kernel<<<ghm, 256, HMMA_SMEM>>>(H2hi, H2lo, W3hi, W3lo, pm_b3, 0,
                                         nullptr, nullptr, HA);

    // TopK over j, sum/8
    topk_kernel<<<(MSMALL * DIM) / 256, 256>>>(HA, T);

    // Aggregate MLP (fp32 SIMT, small)
    cat_kernel<<<(MSMALL * 2 * DIM) / 256, 256>>>(feats, T, CAT);
    sgemm_kernel<<<gsmall, 256>>>(CAT, ag_w1, ag_b1, SA,
                                  MSMALL, DIM, 2 * DIM, 1, nullptr, nullptr,
                                  nullptr, nullptr);
    sgemm_kernel<<<gsmall, 256>>>(SA, ag_w2, ag_b2, SB,
                                  MSMALL, DIM, DIM, 1, nullptr, nullptr,
                                  nullptr, nullptr);
    sgemm_kernel<<<gsmall, 256>>>(SB, ag_w3, ag_b3, SA,
                                  MSMALL, DIM, DIM, 0, nullptr, nullptr,
                                  nullptr, nullptr);

    // Heads
    heads_kernel<<<MSMALL, 128>>>(SA, subject, obj, cs_w, cs_b, cso_w, cso_b, out);
}

// round 4
// speedup vs baseline: 3.0435x; 1.5530x over previous
#include <cuda_runtime.h>
#include <cuda_bf16.h>
#include <cstdint>
#include <cstddef>

// ---------------------------------------------------------------------------
// Problem constants
// ---------------------------------------------------------------------------
#define BSZ 2
#define NP  128
#define DIM 1024
#define GEO 64
#define TOPK 18
#define MBIG (BSZ * NP * NP)     // 32768 pairwise rows
#define MSMALL (BSZ * NP)        // 256 proposal rows

// ---------------------------------------------------------------------------
// Scratch (static device globals)
// ---------------------------------------------------------------------------
__device__ float g_HA[(size_t)MBIG * DIM];       // layer-3 output fp32 (128 MB)
__device__ float g_FA[MSMALL * DIM];
__device__ float g_FB[MSMALL * DIM];
__device__ float g_T[MSMALL * DIM];
__device__ float g_CAT[MSMALL * 2 * DIM];
__device__ float g_SA[MSMALL * DIM];
__device__ float g_SB[MSMALL * DIM];
__device__ float g_P[8 * MSMALL * DIM];          // split-K partials (8 MB)
__device__ unsigned short g_G3hi[MBIG * GEO];    // geo out hi/lo (4 MB each)
__device__ unsigned short g_G3lo[MBIG * GEO];
__device__ unsigned short g_H1hi[(size_t)MBIG * DIM];  // 64 MB each
__device__ unsigned short g_H1lo[(size_t)MBIG * DIM];
__device__ unsigned short g_H2hi[(size_t)MBIG * DIM];
__device__ unsigned short g_H2lo[(size_t)MBIG * DIM];
__device__ unsigned short g_W1hi[DIM * GEO];     // [N,K] w1 geo slice
__device__ unsigned short g_W1lo[DIM * GEO];
__device__ unsigned short g_W2hi[DIM * DIM];     // [N,K] transposed
__device__ unsigned short g_W2lo[DIM * DIM];
__device__ unsigned short g_W3hi[DIM * DIM];
__device__ unsigned short g_W3lo[DIM * DIM];

// ---------------------------------------------------------------------------
// Helpers (sm_80+ only: cp.async, ldmatrix, mma.sync — no tcgen05)
// ---------------------------------------------------------------------------
__device__ __forceinline__ uint32_t smem_u32(const void* p) {
    uint32_t a;
    asm("{ .reg .u64 t; cvta.to.shared.u64 t, %1; cvt.u32.u64 %0, t; }"
        : "=r"(a) : "l"(p));
    return a;
}
__device__ __forceinline__ void cp16(uint32_t dst, const void* src) {
    asm volatile("cp.async.cg.shared.global [%0], [%1], 16;" :: "r"(dst), "l"(src));
}
__device__ __forceinline__ void cp_commit() {
    asm volatile("cp.async.commit_group;" ::: "memory");
}
template<int N> __device__ __forceinline__ void cp_wait() {
    asm volatile("cp.async.wait_group %0;" :: "n"(N) : "memory");
}
#define SWZ128(o) ((o) ^ (((o) >> 3) & 0x70))

__device__ __forceinline__ void ldsm4(uint32_t& r0, uint32_t& r1,
                                      uint32_t& r2, uint32_t& r3, uint32_t addr) {
    asm volatile("ldmatrix.sync.aligned.m8n8.x4.shared.b16 {%0,%1,%2,%3}, [%4];"
                 : "=r"(r0), "=r"(r1), "=r"(r2), "=r"(r3) : "r"(addr));
}
__device__ __forceinline__ void mma_bf16(float* c,
                                         const uint32_t* a, const uint32_t* b) {
    asm volatile("mma.sync.aligned.m16n8k16.row.col.f32.bf16.bf16.f32 "
                 "{%0,%1,%2,%3}, {%4,%5,%6,%7}, {%8,%9}, {%0,%1,%2,%3};"
                 : "+f"(c[0]), "+f"(c[1]), "+f"(c[2]), "+f"(c[3])
                 : "r"(a[0]), "r"(a[1]), "r"(a[2]), "r"(a[3]),
                   "r"(b[0]), "r"(b[1]));
}

__device__ __forceinline__ unsigned short f2bf_bits(float v) {
    __nv_bfloat16 h = __float2bfloat16(v);
    return *reinterpret_cast<unsigned short*>(&h);
}
__device__ __forceinline__ float bf_bits2f(unsigned short u) {
    __nv_bfloat16 h = *reinterpret_cast<__nv_bfloat16*>(&u);
    return __bfloat162float(h);
}

// ---------------------------------------------------------------------------
// HMMA big GEMM (K=1024): out = act( A @ B^T + bias ), hi/lo split, fp32 acc.
// CTA tile 128x128; 8 warps 2(M)x4(N); warp tile 64x32. K chunk 64.
// ---------------------------------------------------------------------------
#define KCH 64
#define NKC (DIM / KCH)            // 16
#define STG_BYTES 65536
#define HMMA_SMEM (2 * STG_BYTES + 128)

__global__ void __launch_bounds__(256, 1)
hmma_kernel(const unsigned short* __restrict__ Ahi,
            const unsigned short* __restrict__ Alo,
            const unsigned short* __restrict__ Bhi,
            const unsigned short* __restrict__ Blo,
            const float* __restrict__ bias, int relu,
            unsigned short* __restrict__ outHi,
            unsigned short* __restrict__ outLo,
            float* __restrict__ outF)
{
    extern __shared__ char smem_raw[];
    const uint32_t sbase = (smem_u32(smem_raw) + 127u) & ~127u;
    const int tid = threadIdx.x;
    const int mtile = blockIdx.y, ntile = blockIdx.x;
    const int lane = tid & 31;
    const int w = tid >> 5;
    const int wm = w >> 2;
    const int wn = w & 3;

    float acc[4][4][4];
#pragma unroll
    for (int mf = 0; mf < 4; mf++)
#pragma unroll
        for (int nf = 0; nf < 4; nf++)
#pragma unroll
            for (int e = 0; e < 4; e++) acc[mf][nf][e] = 0.f;

    const unsigned short* srcs[4] = { Ahi, Alo, Bhi, Blo };

    auto load_chunk = [&](int kc, int stg) {
        const uint32_t s0 = sbase + (uint32_t)stg * STG_BYTES;
#pragma unroll
        for (int t4 = 0; t4 < 4; t4++) {
            const unsigned short* src = srcs[t4];
            const int rowbase = (t4 < 2 ? mtile : ntile) << 7;
            const uint32_t dtile = s0 + t4 * 16384u;
#pragma unroll
            for (int it = 0; it < 4; it++) {
                int t = tid + (it << 8);
                int rr = t >> 3, ss = t & 7;
                cp16(dtile + SWZ128((uint32_t)(rr * 128 + ss * 16)),
                     src + (size_t)(rowbase + rr) * DIM + kc * KCH + ss * 8);
            }
        }
        cp_commit();
    };

    const int a_rl = lane & 15;
    const int a_cl = (lane >> 4) << 3;
    const int b_rl = (lane & 7) + ((lane >> 4) << 3);
    const int b_cl = ((lane >> 3) & 1) << 3;

    auto compute = [&](int stg) {
        const uint32_t s0 = sbase + (uint32_t)stg * STG_BYTES;
        const uint32_t sAhi = s0, sAlo = s0 + 16384u;
        const uint32_t sBhi = s0 + 32768u, sBlo = s0 + 49152u;
#pragma unroll
        for (int ks = 0; ks < 4; ks++) {
            const int k0 = ks * 16;
            uint32_t bh[4][2], bl[4][2];
#pragma unroll
            for (int np = 0; np < 2; np++) {
                const int n0 = wn * 32 + np * 16;
                const uint32_t off =
                    SWZ128((uint32_t)((n0 + b_rl) * 128 + (k0 + b_cl) * 2));
                uint32_t r0, r1, r2, r3;
                ldsm4(r0, r1, r2, r3, sBhi + off);
                bh[np * 2][0] = r0; bh[np * 2][1] = r1;
                bh[np * 2 + 1][0] = r2; bh[np * 2 + 1][1] = r3;
                ldsm4(r0, r1, r2, r3, sBlo + off);
                bl[np * 2][0] = r0; bl[np * 2][1] = r1;
                bl[np * 2 + 1][0] = r2; bl[np * 2 + 1][1] = r3;
            }
            uint32_t af[4][4];
#pragma unroll
            for (int mf = 0; mf < 4; mf++) {
                const int m0 = wm * 64 + mf * 16;
                const uint32_t off =
                    SWZ128((uint32_t)((m0 + a_rl) * 128 + (k0 + a_cl) * 2));
                ldsm4(af[mf][0], af[mf][1], af[mf][2], af[mf][3], sAhi + off);
            }
#pragma unroll
            for (int mf = 0; mf < 4; mf++)
#pragma unroll
                for (int nf = 0; nf < 4; nf++) {
                    mma_bf16(acc[mf][nf], af[mf], bh[nf]);
                    mma_bf16(acc[mf][nf], af[mf], bl[nf]);
                }
#pragma unroll
            for (int mf = 0; mf < 4; mf++) {
                const int m0 = wm * 64 + mf * 16;
                const uint32_t off =
                    SWZ128((uint32_t)((m0 + a_rl) * 128 + (k0 + a_cl) * 2));
                ldsm4(af[mf][0], af[mf][1], af[mf][2], af[mf][3], sAlo + off);
            }
#pragma unroll
            for (int mf = 0; mf < 4; mf++)
#pragma unroll
                for (int nf = 0; nf < 4; nf++)
                    mma_bf16(acc[mf][nf], af[mf], bh[nf]);
        }
    };

    load_chunk(0, 0);
    for (int kc = 0; kc < NKC; kc++) {
        if (kc + 1 < NKC) {
            load_chunk(kc + 1, (kc + 1) & 1);
            cp_wait<1>();
        } else {
            cp_wait<0>();
        }
        __syncthreads();
        compute(kc & 1);
        __syncthreads();
    }

    const int rl = lane >> 2;
    const int cl = (lane & 3) << 1;
#pragma unroll
    for (int mf = 0; mf < 4; mf++) {
        const int m_base = (mtile << 7) + wm * 64 + mf * 16 + rl;
#pragma unroll
        for (int nf = 0; nf < 4; nf++) {
            const int n = (ntile << 7) + wn * 32 + nf * 8 + cl;
            const float b0 = bias[n], b1 = bias[n + 1];
#pragma unroll
            for (int half = 0; half < 2; half++) {
                const int m = m_base + half * 8;
                float v0 = acc[mf][nf][half * 2 + 0] + b0;
                float v1 = acc[mf][nf][half * 2 + 1] + b1;
                if (relu) { v0 = fmaxf(v0, 0.f); v1 = fmaxf(v1, 0.f); }
                if (outF) {
                    float2 f2; f2.x = v0; f2.y = v1;
                    *(float2*)(outF + (size_t)m * DIM + n) = f2;
                } else {
                    unsigned short h0 = f2bf_bits(v0);
                    unsigned short h1 = f2bf_bits(v1);
                    unsigned short l0 = f2bf_bits(v0 - bf_bits2f(h0));
                    unsigned short l1 = f2bf_bits(v1 - bf_bits2f(h1));
                    *(uint32_t*)(outHi + (size_t)m * DIM + n) =
                        (uint32_t)h0 | ((uint32_t)h1 << 16);
                    *(uint32_t*)(outLo + (size_t)m * DIM + n) =
                        (uint32_t)l0 | ((uint32_t)l1 << 16);
                }
            }
        }
    }
}

// ---------------------------------------------------------------------------
// Layer-1 HMMA (K=64): H1 = relu( G3 @ W1g^T + FA_j + FB_i + b1 ), hi/lo out.
// A = G3 [MBIG, 64] hi/lo, B = W1g [1024(N), 64(K)] hi/lo. Single smem stage.
// ---------------------------------------------------------------------------
#define L1_SMEM (4 * 16384 + 128)

__global__ void __launch_bounds__(256, 2)
hmma_l1_kernel(const unsigned short* __restrict__ Ahi,
               const unsigned short* __restrict__ Alo,
               const unsigned short* __restrict__ Bhi,
               const unsigned short* __restrict__ Blo,
               const float* __restrict__ bias,
               const float* __restrict__ FA,    // indexed by (b,j)
               const float* __restrict__ FB,    // indexed by (b,i)
               unsigned short* __restrict__ outHi,
               unsigned short* __restrict__ outLo)
{
    extern __shared__ char smem_raw[];
    const uint32_t sbase = (smem_u32(smem_raw) + 127u) & ~127u;
    const int tid = threadIdx.x;
    const int mtile = blockIdx.y, ntile = blockIdx.x;
    const int lane = tid & 31;
    const int w = tid >> 5;
    const int wm = w >> 2;
    const int wn = w & 3;

    // load 4 tiles of [128 rows x 64 cols] bf16 (128 B/row, SW128)
    const unsigned short* srcs[4] = { Ahi, Alo, Bhi, Blo };
#pragma unroll
    for (int t4 = 0; t4 < 4; t4++) {
        const unsigned short* src = srcs[t4];
        const int rowbase = (t4 < 2 ? mtile : ntile) << 7;
        const uint32_t dtile = sbase + t4 * 16384u;
#pragma unroll
        for (int it = 0; it < 4; it++) {
            int t = tid + (it << 8);
            int rr = t >> 3, ss = t & 7;
            cp16(dtile + SWZ128((uint32_t)(rr * 128 + ss * 16)),
                 src + (size_t)(rowbase + rr) * GEO + ss * 8);
        }
    }
    cp_commit();

    float acc[4][4][4];
#pragma unroll
    for (int mf = 0; mf < 4; mf++)
#pragma unroll
        for (int nf = 0; nf < 4; nf++)
#pragma unroll
            for (int e = 0; e < 4; e++) acc[mf][nf][e] = 0.f;

    const int a_rl = lane & 15;
    const int a_cl = (lane >> 4) << 3;
    const int b_rl = (lane & 7) + ((lane >> 4) << 3);
    const int b_cl = ((lane >> 3) & 1) << 3;

    cp_wait<0>();
    __syncthreads();

    const uint32_t sAhi = sbase, sAlo = sbase + 16384u;
    const uint32_t sBhi = sbase + 32768u, sBlo = sbase + 49152u;
#pragma unroll
    for (int ks = 0; ks < 4; ks++) {
        const int k0 = ks * 16;
        uint32_t bh[4][2], bl[4][2];
#pragma unroll
        for (int np = 0; np < 2; np++) {
            const int n0 = wn * 32 + np * 16;
            const uint32_t off =
                SWZ128((uint32_t)((n0 + b_rl) * 128 + (k0 + b_cl) * 2));
            uint32_t r0, r1, r2, r3;
            ldsm4(r0, r1, r2, r3, sBhi + off);
            bh[np * 2][0] = r0; bh[np * 2][1] = r1;
            bh[np * 2 + 1][0] = r2; bh[np * 2 + 1][1] = r3;
            ldsm4(r0, r1, r2, r3, sBlo + off);
            bl[np * 2][0] = r0; bl[np * 2][1] = r1;
            bl[np * 2 + 1][0] = r2; bl[np * 2 + 1][1] = r3;
        }
        uint32_t af[4][4];
#pragma unroll
        for (int mf = 0; mf < 4; mf++) {
            const int m0 = wm * 64 + mf * 16;
            const uint32_t off =
                SWZ128((uint32_t)((m0 + a_rl) * 128 + (k0 + a_cl) * 2));
            ldsm4(af[mf][0], af[mf][1], af[mf][2], af[mf][3], sAhi + off);
        }
#pragma unroll
        for (int mf = 0; mf < 4; mf++)
#pragma unroll
            for (int nf = 0; nf < 4; nf++) {
                mma_bf16(acc[mf][nf], af[mf], bh[nf]);
                mma_bf16(acc[mf][nf], af[mf], bl[nf]);
            }
#pragma unroll
        for (int mf = 0; mf < 4; mf++) {
            const int m0 = wm * 64 + mf * 16;
            const uint32_t off =
                SWZ128((uint32_t)((m0 + a_rl) * 128 + (k0 + a_cl) * 2));
            ldsm4(af[mf][0], af[mf][1], af[mf][2], af[mf][3], sAlo + off);
        }
#pragma unroll
        for (int mf = 0; mf < 4; mf++)
#pragma unroll
            for (int nf = 0; nf < 4; nf++)
                mma_bf16(acc[mf][nf], af[mf], bh[nf]);
    }

    const int rl = lane >> 2;
    const int cl = (lane & 3) << 1;
#pragma unroll
    for (int mf = 0; mf < 4; mf++) {
        const int m_base = (mtile << 7) + wm * 64 + mf * 16 + rl;
#pragma unroll
        for (int nf = 0; nf < 4; nf++) {
            const int n = (ntile << 7) + wn * 32 + nf * 8 + cl;
            const float b0 = bias[n], b1 = bias[n + 1];
#pragma unroll
            for (int half = 0; half < 2; half++) {
                const int m = m_base + half * 8;
                const int j = m & (NP - 1);
                const int bi = m >> 7;
                const int bb = bi >> 7;
                const float* aJ = FA + (size_t)((bb << 7) + j) * DIM;
                const float* aI = FB + (size_t)bi * DIM;
                float v0 = acc[mf][nf][half * 2 + 0] + b0 + aJ[n] + aI[n];
                float v1 = acc[mf][nf][half * 2 + 1] + b1 + aJ[n + 1] + aI[n + 1];
                v0 = fmaxf(v0, 0.f); v1 = fmaxf(v1, 0.f);
                unsigned short h0 = f2bf_bits(v0);
                unsigned short h1 = f2bf_bits(v1);
                unsigned short l0 = f2bf_bits(v0 - bf_bits2f(h0));
                unsigned short l1 = f2bf_bits(v1 - bf_bits2f(h1));
                *(uint32_t*)(outHi + (size_t)m * DIM + n) =
                    (uint32_t)h0 | ((uint32_t)h1 << 16);
                *(uint32_t*)(outLo + (size_t)m * DIM + n) =
                    (uint32_t)l0 | ((uint32_t)l1 << 16);
            }
        }
    }
}

// ---------------------------------------------------------------------------
// Split-K SGEMM for small-M GEMMs: P[slice] = A[:, slice] @ B[slice, :]
// CTA tile 64(M) x 128(N); thread micro 8x4. KSL elements per slice.
// ---------------------------------------------------------------------------
#define SKM 64
#define SKN 128

__global__ __launch_bounds__(256)
void sgemm_splitk(const float* __restrict__ A, const float* __restrict__ B,
                  float* __restrict__ P, int M, int N, int K, int KSL)
{
    __shared__ float As[16][SKM + 4];
    __shared__ float Bs[16][SKN];

    const int slice = blockIdx.z;
    const int bm = blockIdx.y * SKM;
    const int bn = blockIdx.x * SKN;
    const int tid = threadIdx.x;
    const int arow = tid >> 2, acol = (tid & 3) << 2;
    const int brow = tid >> 5, bcol = (tid & 31) << 2;
    const int tx = tid & 31;        // n micro: tx*4
    const int ty = tid >> 5;        // m micro: ty*8

    float acc[8][4];
#pragma unroll
    for (int a = 0; a < 8; a++)
#pragma unroll
        for (int b = 0; b < 4; b++) acc[a][b] = 0.f;

    const float* Aptr = A + (size_t)(bm + arow) * K + slice * KSL + acol;
    const float* Bptr = B + (size_t)(slice * KSL + brow) * N + bn + bcol;

    for (int k0 = 0; k0 < KSL; k0 += 16) {
        float4 a0 = *(const float4*)(Aptr + k0);
        float4 b0 = *(const float4*)(Bptr + (size_t)k0 * N);
        float4 b1 = *(const float4*)(Bptr + (size_t)(k0 + 8) * N);
        __syncthreads();
        As[acol + 0][arow] = a0.x; As[acol + 1][arow] = a0.y;
        As[acol + 2][arow] = a0.z; As[acol + 3][arow] = a0.w;
        *(float4*)&Bs[brow][bcol] = b0;
        *(float4*)&Bs[brow + 8][bcol] = b1;
        __syncthreads();
#pragma unroll
        for (int kk = 0; kk < 16; kk++) {
            float ra[8], rb[4];
#pragma unroll
            for (int a = 0; a < 8; a++) ra[a] = As[kk][ty * 8 + a];
#pragma unroll
            for (int b = 0; b < 4; b++) rb[b] = Bs[kk][tx * 4 + b];
#pragma unroll
            for (int a = 0; a < 8; a++)
#pragma unroll
                for (int b = 0; b < 4; b++)
                    acc[a][b] = fmaf(ra[a], rb[b], acc[a][b]);
        }
    }

    float* Pp = P + (size_t)slice * M * N;
#pragma unroll
    for (int a = 0; a < 8; a++) {
        int m = bm + ty * 8 + a;
        float4 v;
        v.x = acc[a][0]; v.y = acc[a][1]; v.z = acc[a][2]; v.w = acc[a][3];
        *(float4*)(Pp + (size_t)m * N + bn + tx * 4) = v;
    }
}

__global__ __launch_bounds__(256)
void skreduce(const float* __restrict__ P, int nsl,
              const float* __restrict__ bias, int relu,
              float* __restrict__ C, int MN, int N)
{
    int idx = blockIdx.x * blockDim.x + threadIdx.x;
    if (idx >= MN) return;
    float s = 0.f;
    for (int sl = 0; sl < nsl; sl++) s += P[(size_t)sl * MN + idx];
    if (bias) s += bias[idx % N];
    if (relu) s = fmaxf(s, 0.f);
    C[idx] = s;
}

// ---------------------------------------------------------------------------
// Weight transpose + bf16 hi/lo split:  W[Kd, Nd] -> Whi/Wlo [Nd, Kd]
// ---------------------------------------------------------------------------
__global__ void wsplit_kernel(const float* __restrict__ W,
                              unsigned short* __restrict__ Whi,
                              unsigned short* __restrict__ Wlo,
                              int Kd, int Nd)
{
    __shared__ float tile[32][33];
    const int n0 = blockIdx.x * 32, k0 = blockIdx.y * 32;
    const int tx = threadIdx.x, ty = threadIdx.y;   // 32 x 8
#pragma unroll
    for (int i = 0; i < 32; i += 8)
        tile[ty + i][tx] = W[(size_t)(k0 + ty + i) * Nd + n0 + tx];
    __syncthreads();
#pragma unroll
    for (int i = 0; i < 32; i += 8) {
        float v = tile[tx][ty + i];
        unsigned short hb = f2bf_bits(v);
        unsigned short lb = f2bf_bits(v - bf_bits2f(hb));
        size_t idx = (size_t)(n0 + ty + i) * Kd + k0 + tx;
        Whi[idx] = hb;
        Wlo[idx] = lb;
    }
}

// ---------------------------------------------------------------------------
// Geo embedding + 3-layer 64-wide MLP (fused) -> bf16 hi/lo output
// ---------------------------------------------------------------------------
__global__ __launch_bounds__(128)
void geo_kernel(const float* __restrict__ prop,
                const float* __restrict__ w1, const float* __restrict__ b1,
                const float* __restrict__ w2, const float* __restrict__ b2,
                const float* __restrict__ w3, const float* __restrict__ b3,
                unsigned short* __restrict__ G3hi,
                unsigned short* __restrict__ G3lo)
{
    __shared__ float sw1[GEO * GEO], sw2[GEO * GEO], sw3[GEO * GEO];
    __shared__ float sb1[GEO], sb2[GEO], sb3[GEO];
    __shared__ float esm[128 * 65];

    const int tid = threadIdx.x;
    for (int t = tid; t < GEO * GEO; t += blockDim.x) {
        sw1[t] = w1[t]; sw2[t] = w2[t]; sw3[t] = w3[t];
    }
    for (int t = tid; t < GEO; t += blockDim.x) {
        sb1[t] = b1[t]; sb2[t] = b2[t]; sb3[t] = b3[t];
    }
    __syncthreads();

    const int row = blockIdx.x * blockDim.x + tid;
    const int b = row >> 14;
    const int i = (row >> 7) & (NP - 1);
    const int j = row & (NP - 1);

    const float* pi = prop + ((size_t)(b * NP + i)) * 4;
    const float* pj = prop + ((size_t)(b * NP + j)) * 4;
    float wi = pi[2] - pi[0] + 1.f, hi = pi[3] - pi[1] + 1.f;
    float wj = pj[2] - pj[0] + 1.f, hj = pj[3] - pj[1] + 1.f;
    float cxi = 0.5f * (pi[0] + pi[2]), cyi = 0.5f * (pi[1] + pi[3]);
    float cxj = 0.5f * (pj[0] + pj[2]), cyj = 0.5f * (pj[1] + pj[3]);

    float pos[4];
    pos[0] = (cxi - cxj) / wj;
    pos[1] = (cyi - cyj) / hj;
    pos[2] = wi / wj;
    pos[3] = hi / hj;

    const float dm[8] = {1.0f, 2.3713737f, 5.6234133f, 13.335215f,
                         31.622777f, 74.989421f, 177.82794f, 421.69650f};

    float* my = &esm[tid * 65];
#pragma unroll
    for (int p = 0; p < 4; p++) {
        float lp = logf(fmaxf(fabsf(pos[p]), 1e-3f)) * 100.f;
#pragma unroll
        for (int r = 0; r < 8; r++) {
            float arg = lp / dm[r];
            float s, c;
            sincosf(arg, &s, &c);
            my[p * 16 + r] = s;
            my[p * 16 + 8 + r] = c;
        }
    }

    float acc[GEO];
#pragma unroll
    for (int o = 0; o < GEO; o++) acc[o] = sb1[o];
    for (int k = 0; k < GEO; k++) {
        float ek = my[k];
        const float* wr = &sw1[k * GEO];
#pragma unroll
        for (int o = 0; o < GEO; o++) acc[o] = fmaf(ek, wr[o], acc[o]);
    }
#pragma unroll
    for (int o = 0; o < GEO; o++) my[o] = fmaxf(acc[o], 0.f);

#pragma unroll
    for (int o = 0; o < GEO; o++) acc[o] = sb2[o];
    for (int k = 0; k < GEO; k++) {
        float ek = my[k];
        const float* wr = &sw2[k * GEO];
#pragma unroll
        for (int o = 0; o < GEO; o++) acc[o] = fmaf(ek, wr[o], acc[o]);
    }
#pragma unroll
    for (int o = 0; o < GEO; o++) my[o] = fmaxf(acc[o], 0.f);

#pragma unroll
    for (int o = 0; o < GEO; o++) acc[o] = sb3[o];
    for (int k = 0; k < GEO; k++) {
        float ek = my[k];
        const float* wr = &sw3[k * GEO];
#pragma unroll
        for (int o = 0; o < GEO; o++) acc[o] = fmaf(ek, wr[o], acc[o]);
    }
    unsigned short* oh = G3hi + (size_t)row * GEO;
    unsigned short* ol = G3lo + (size_t)row * GEO;
#pragma unroll
    for (int o = 0; o < GEO; o++) {
        unsigned short hb = f2bf_bits(acc[o]);
        oh[o] = hb;
        ol[o] = f2bf_bits(acc[o] - bf_bits2f(hb));
    }
}

// ---------------------------------------------------------------------------
// TopK + concat + heads
// ---------------------------------------------------------------------------
__global__ __launch_bounds__(256)
void topk_kernel(const float* __restrict__ H, float* __restrict__ T)
{
    int idx = blockIdx.x * blockDim.x + threadIdx.x;
    int c = idx & (DIM - 1);
    int bi = idx >> 10;
    const float* p = H + ((size_t)bi * NP) * DIM + c;

    float t[TOPK];
#pragma unroll
    for (int s = 0; s < TOPK; s++) t[s] = -3.4e38f;

    for (int j = 0; j < NP; j++) {
        float v = p[(size_t)j * DIM];
        if (v > t[TOPK - 1]) {
            t[TOPK - 1] = v;
#pragma unroll
            for (int s = TOPK - 1; s > 0; s--) {
                if (t[s] > t[s - 1]) {
                    float tmp = t[s - 1]; t[s - 1] = t[s]; t[s] = tmp;
                }
            }
        }
    }
    float sum = 0.f;
#pragma unroll
    for (int s = 0; s < TOPK; s++) sum += t[s];
    T[idx] = sum * 0.125f;
}

__global__ void cat_kernel(const float* __restrict__ feats,
                           const float* __restrict__ T,
                           float* __restrict__ CAT)
{
    int idx = blockIdx.x * blockDim.x + threadIdx.x;
    int m = idx >> 11;
    int k = idx & 2047;
    float v = (k < DIM) ? feats[(size_t)m * DIM + k]
                        : T[(size_t)m * DIM + (k - DIM)];
    CAT[idx] = v;
}

__global__ __launch_bounds__(128)
void heads_kernel(const float* __restrict__ X,
                  const float* __restrict__ subject,
                  const float* __restrict__ obj,
                  const float* __restrict__ cs_w, const float* __restrict__ cs_b,
                  const float* __restrict__ cso_w, const float* __restrict__ cso_b,
                  float* __restrict__ out)
{
    int row = blockIdx.x;
    int b = row >> 7;
    int tid = threadIdx.x;

    float as = 0.f, ao = 0.f;
    for (int k = tid; k < DIM; k += 128) {
        float xv = X[(size_t)row * DIM + k];
        float sv = subject[(size_t)b * DIM + k];
        float ov = obj[(size_t)b * DIM + k];
        as += xv * cs_w[k] + sv * cs_w[DIM + k];
        ao += xv * cso_w[k] + ov * cso_w[DIM + k];
    }
    __shared__ float rs[128], ro[128];
    rs[tid] = as; ro[tid] = ao;
    __syncthreads();
    for (int s = 64; s > 0; s >>= 1) {
        if (tid < s) { rs[tid] += rs[tid + s]; ro[tid] += ro[tid + s]; }
        __syncthreads();
    }
    if (tid == 0) {
        float s1 = rs[0] + cs_b[0];
        float s2 = ro[0] + cso_b[0];
        out[row * 2 + 0] = 1.f / (1.f + expf(-s1));
        out[row * 2 + 1] = 1.f / (1.f + expf(-s2));
    }
}

// ---------------------------------------------------------------------------
// Launch
// ---------------------------------------------------------------------------
extern "C" void kernel_launch(void* const* d_in, const int* in_sizes, int n_in,
                              void* d_out, int out_size)
{
    const float* feats   = (const float*)d_in[0];
    const float* subject = (const float*)d_in[1];
    const float* obj     = (const float*)d_in[2];
    const float* prop    = (const float*)d_in[3];
    const float* gp_w1 = (const float*)d_in[4];
    const float* gp_b1 = (const float*)d_in[5];
    const float* gp_w2 = (const float*)d_in[6];
    const float* gp_b2 = (const float*)d_in[7];
    const float* gp_w3 = (const float*)d_in[8];
    const float* gp_b3 = (const float*)d_in[9];
    const float* pm_w1 = (const float*)d_in[10];
    const float* pm_b1 = (const float*)d_in[11];
    const float* pm_w2 = (const float*)d_in[12];
    const float* pm_b2 = (const float*)d_in[13];
    const float* pm_w3 = (const float*)d_in[14];
    const float* pm_b3 = (const float*)d_in[15];
    const float* ag_w1 = (const float*)d_in[16];
    const float* ag_b1 = (const float*)d_in[17];
    const float* ag_w2 = (const float*)d_in[18];
    const float* ag_b2 = (const float*)d_in[19];
    const float* ag_w3 = (const float*)d_in[20];
    const float* ag_b3 = (const float*)d_in[21];
    const float* cs_w  = (const float*)d_in[22];
    const float* cs_b  = (const float*)d_in[23];
    const float* cso_w = (const float*)d_in[24];
    const float* cso_b = (const float*)d_in[25];
    float* out = (float*)d_out;

    float *HA, *FA, *FB, *T, *CAT, *SA, *SB, *P;
    unsigned short *G3hi, *G3lo, *H1hi, *H1lo, *H2hi, *H2lo;
    unsigned short *W1hi, *W1lo, *W2hi, *W2lo, *W3hi, *W3lo;
    cudaGetSymbolAddress((void**)&HA, g_HA);
    cudaGetSymbolAddress((void**)&FA, g_FA);
    cudaGetSymbolAddress((void**)&FB, g_FB);
    cudaGetSymbolAddress((void**)&T,  g_T);
    cudaGetSymbolAddress((void**)&CAT, g_CAT);
    cudaGetSymbolAddress((void**)&SA, g_SA);
    cudaGetSymbolAddress((void**)&SB, g_SB);
    cudaGetSymbolAddress((void**)&P,  g_P);
    cudaGetSymbolAddress((void**)&G3hi, g_G3hi);
    cudaGetSymbolAddress((void**)&G3lo, g_G3lo);
    cudaGetSymbolAddress((void**)&H1hi, g_H1hi);
    cudaGetSymbolAddress((void**)&H1lo, g_H1lo);
    cudaGetSymbolAddress((void**)&H2hi, g_H2hi);
    cudaGetSymbolAddress((void**)&H2lo, g_H2lo);
    cudaGetSymbolAddress((void**)&W1hi, g_W1hi);
    cudaGetSymbolAddress((void**)&W1lo, g_W1lo);
    cudaGetSymbolAddress((void**)&W2hi, g_W2hi);
    cudaGetSymbolAddress((void**)&W2lo, g_W2lo);
    cudaGetSymbolAddress((void**)&W3hi, g_W3hi);
    cudaGetSymbolAddress((void**)&W3lo, g_W3lo);

    cudaFuncSetAttribute(hmma_kernel,
                         cudaFuncAttributeMaxDynamicSharedMemorySize, HMMA_SMEM);
    cudaFuncSetAttribute(hmma_l1_kernel,
                         cudaFuncAttributeMaxDynamicSharedMemorySize, L1_SMEM);

    dim3 ghm(DIM / 128, MBIG / 128);          // (8, 256)
    dim3 gws(DIM / 32, DIM / 32);             // w2/w3 transpose
    dim3 gws1(DIM / 32, GEO / 32);            // w1 geo slice transpose
    const int MN = MSMALL * DIM;              // 262144

    // Weight transpose + split (tiny)
    wsplit_kernel<<<gws, dim3(32, 8)>>>(pm_w2, W2hi, W2lo, DIM, DIM);
    wsplit_kernel<<<gws, dim3(32, 8)>>>(pm_w3, W3hi, W3lo, DIM, DIM);
    wsplit_kernel<<<gws1, dim3(32, 8)>>>(pm_w1 + (size_t)2 * DIM * DIM,
                                         W1hi, W1lo, GEO, DIM);

    // FA/FB precompute via split-K (K=1024, 4 slices)
    dim3 gsk(DIM / SKN, MSMALL / SKM, 4);     // (8, 4, 4)
    sgemm_splitk<<<gsk, 256>>>(feats, pm_w1, P, MSMALL, DIM, DIM, 256);
    skreduce<<<MN / 256, 256>>>(P, 4, nullptr, 0, FA, MN, DIM);
    sgemm_splitk<<<gsk, 256>>>(feats, pm_w1 + (size_t)DIM * DIM, P,
                               MSMALL, DIM, DIM, 256);
    skreduce<<<MN / 256, 256>>>(P, 4, nullptr, 0, FB, MN, DIM);

    // Geo embedding + geo MLP -> hi/lo bf16
    geo_kernel<<<MBIG / 128, 128>>>(prop, gp_w1, gp_b1, gp_w2, gp_b2,
                                    gp_w3, gp_b3, G3hi, G3lo);

    // Pairwise layer 1 (HMMA, K=64) -> H1 hi/lo
    hmma_l1_kernel<<<ghm, 256, L1_SMEM>>>(G3hi, G3lo, W1hi, W1lo, pm_b1,
                                          FA, FB, H1hi, H1lo);

    // Pairwise layer 2 (HMMA) -> H2 hi/lo, relu
    hmma_kernel<<<ghm, 256, HMMA_SMEM>>>(H1hi, H1lo, W2hi, W2lo, pm_b2, 1,
                                         H2hi, H2lo, nullptr);
    // Pairwise layer 3 (HMMA) -> HA fp32, linear
    hmma_kernel<<<ghm, 256, HMMA_SMEM>>>(H2hi, H2lo, W3hi, W3lo, pm_b3, 0,
                                         nullptr, nullptr, HA);

    // TopK over j, sum/8
    topk_kernel<<<MN / 256, 256>>>(HA, T);

    // Aggregate MLP via split-K
    cat_kernel<<<(MSMALL * 2 * DIM) / 256, 256>>>(feats, T, CAT);
    dim3 gsk8(DIM / SKN, MSMALL / SKM, 8);    // K=2048, 8 slices
    sgemm_splitk<<<gsk8, 256>>>(CAT, ag_w1, P, MSMALL, DIM, 2 * DIM, 256);
    skreduce<<<MN / 256, 256>>>(P, 8, ag_b1, 1, SA, MN, DIM);
    sgemm_splitk<<<gsk, 256>>>(SA, ag_w2, P, MSMALL, DIM, DIM, 256);
    skreduce<<<MN / 256, 256>>>(P, 4, ag_b2, 1, SB, MN, DIM);
    sgemm_splitk<<<gsk, 256>>>(SB, ag_w3, P, MSMALL, DIM, DIM, 256);
    skreduce<<<MN / 256, 256>>>(P, 4, ag_b3, 0, SA, MN, DIM);

    // Heads
    heads_kernel<<<MSMALL, 128>>>(SA, subject, obj, cs_w, cs_b, cso_w, cso_b, out);
}

// round 5
// speedup vs baseline: 6.0511x; 1.9882x over previous
#include <cuda_runtime.h>
#include <cuda_fp16.h>
#include <cstdint>
#include <cstddef>

// ---------------------------------------------------------------------------
// Problem constants
// ---------------------------------------------------------------------------
#define BSZ 2
#define NP  128
#define DIM 1024
#define GEO 64
#define TOPK 18
#define MBIG (BSZ * NP * NP)     // 32768 pairwise rows
#define MSMALL (BSZ * NP)        // 256 proposal rows

// ---------------------------------------------------------------------------
// Scratch (static device globals)
// ---------------------------------------------------------------------------
__device__ float g_HA[(size_t)MBIG * DIM];       // layer-3 output fp32 (128 MB)
__device__ float g_FA[MSMALL * DIM];
__device__ float g_FB[MSMALL * DIM];
__device__ float g_T[MSMALL * DIM];
__device__ float g_CAT[MSMALL * 2 * DIM];
__device__ float g_SA[MSMALL * DIM];
__device__ float g_SB[MSMALL * DIM];
__device__ float g_P[16 * MSMALL * DIM];         // split-K partials (16 MB)
__device__ unsigned short g_G3[MBIG * GEO];      // geo out fp16 (4 MB)
__device__ unsigned short g_H1[(size_t)MBIG * DIM];  // fp16, 64 MB
__device__ unsigned short g_H2[(size_t)MBIG * DIM];  // fp16, 64 MB
__device__ unsigned short g_W1[DIM * GEO];       // [N,K] w1 geo slice fp16
__device__ unsigned short g_W2[DIM * DIM];       // [N,K] fp16
__device__ unsigned short g_W3[DIM * DIM];       // [N,K] fp16

// ---------------------------------------------------------------------------
// Helpers (sm_80+ only: cp.async, ldmatrix, mma.sync)
// ---------------------------------------------------------------------------
__device__ __forceinline__ uint32_t smem_u32(const void* p) {
    uint32_t a;
    asm("{ .reg .u64 t; cvta.to.shared.u64 t, %1; cvt.u32.u64 %0, t; }"
        : "=r"(a) : "l"(p));
    return a;
}
__device__ __forceinline__ void cp16(uint32_t dst, const void* src) {
    asm volatile("cp.async.cg.shared.global [%0], [%1], 16;" :: "r"(dst), "l"(src));
}
__device__ __forceinline__ void cp_commit() {
    asm volatile("cp.async.commit_group;" ::: "memory");
}
template<int N> __device__ __forceinline__ void cp_wait() {
    asm volatile("cp.async.wait_group %0;" :: "n"(N) : "memory");
}
#define SWZ128(o) ((o) ^ (((o) >> 3) & 0x70))

__device__ __forceinline__ void ldsm4(uint32_t& r0, uint32_t& r1,
                                      uint32_t& r2, uint32_t& r3, uint32_t addr) {
    asm volatile("ldmatrix.sync.aligned.m8n8.x4.shared.b16 {%0,%1,%2,%3}, [%4];"
                 : "=r"(r0), "=r"(r1), "=r"(r2), "=r"(r3) : "r"(addr));
}
__device__ __forceinline__ void mma_f16(float* c,
                                        const uint32_t* a, const uint32_t* b) {
    asm volatile("mma.sync.aligned.m16n8k16.row.col.f32.f16.f16.f32 "
                 "{%0,%1,%2,%3}, {%4,%5,%6,%7}, {%8,%9}, {%0,%1,%2,%3};"
                 : "+f"(c[0]), "+f"(c[1]), "+f"(c[2]), "+f"(c[3])
                 : "r"(a[0]), "r"(a[1]), "r"(a[2]), "r"(a[3]),
                   "r"(b[0]), "r"(b[1]));
}

__device__ __forceinline__ unsigned short f2h_bits(float v) {
    __half h = __float2half_rn(v);
    return *reinterpret_cast<unsigned short*>(&h);
}

// ---------------------------------------------------------------------------
// fp16 HMMA big GEMM (K=1024): out = act( A @ B^T + bias ), fp32 acc.
// A [MBIG, DIM] fp16 row-major; B [DIM(N), DIM(K)] fp16 row-major.
// CTA tile 128x128; 8 warps 2(M)x4(N); warp tile 64x32.
// K chunk 64 (128B rows, SW128). 3-stage cp.async pipeline (32 KB/stage).
// ---------------------------------------------------------------------------
#define KCH 64
#define NKC (DIM / KCH)            // 16
#define STG_BYTES 32768
#define HMMA_SMEM (3 * STG_BYTES + 128)

__global__ void __launch_bounds__(256, 2)
hmma_kernel(const unsigned short* __restrict__ A,
            const unsigned short* __restrict__ B,
            const float* __restrict__ bias, int relu,
            unsigned short* __restrict__ outH,
            float* __restrict__ outF)
{
    extern __shared__ char smem_raw[];
    const uint32_t sbase = (smem_u32(smem_raw) + 127u) & ~127u;
    const int tid = threadIdx.x;
    const int mtile = blockIdx.y, ntile = blockIdx.x;
    const int lane = tid & 31;
    const int w = tid >> 5;
    const int wm = w >> 2;
    const int wn = w & 3;

    float acc[4][4][4];
#pragma unroll
    for (int mf = 0; mf < 4; mf++)
#pragma unroll
        for (int nf = 0; nf < 4; nf++)
#pragma unroll
            for (int e = 0; e < 4; e++) acc[mf][nf][e] = 0.f;

    auto load_chunk = [&](int kc, int stg) {
        const uint32_t s0 = sbase + (uint32_t)stg * STG_BYTES;
        // A tile [128 x 64] fp16
#pragma unroll
        for (int it = 0; it < 4; it++) {
            int t = tid + (it << 8);
            int rr = t >> 3, ss = t & 7;
            cp16(s0 + SWZ128((uint32_t)(rr * 128 + ss * 16)),
                 A + (size_t)((mtile << 7) + rr) * DIM + kc * KCH + ss * 8);
        }
        // B tile [128 x 64] fp16
#pragma unroll
        for (int it = 0; it < 4; it++) {
            int t = tid + (it << 8);
            int rr = t >> 3, ss = t & 7;
            cp16(s0 + 16384u + SWZ128((uint32_t)(rr * 128 + ss * 16)),
                 B + (size_t)((ntile << 7) + rr) * DIM + kc * KCH + ss * 8);
        }
        cp_commit();
    };

    const int a_rl = lane & 15;
    const int a_cl = (lane >> 4) << 3;
    const int b_rl = (lane & 7) + ((lane >> 4) << 3);
    const int b_cl = ((lane >> 3) & 1) << 3;

    auto compute = [&](int stg) {
        const uint32_t s0 = sbase + (uint32_t)stg * STG_BYTES;
        const uint32_t sA = s0, sB = s0 + 16384u;
#pragma unroll
        for (int ks = 0; ks < 4; ks++) {
            const int k0 = ks * 16;
            uint32_t bf[4][2];
#pragma unroll
            for (int np = 0; np < 2; np++) {
                const int n0 = wn * 32 + np * 16;
                const uint32_t off =
                    SWZ128((uint32_t)((n0 + b_rl) * 128 + (k0 + b_cl) * 2));
                uint32_t r0, r1, r2, r3;
                ldsm4(r0, r1, r2, r3, sB + off);
                bf[np * 2][0] = r0; bf[np * 2][1] = r1;
                bf[np * 2 + 1][0] = r2; bf[np * 2 + 1][1] = r3;
            }
            uint32_t af[4][4];
#pragma unroll
            for (int mf = 0; mf < 4; mf++) {
                const int m0 = wm * 64 + mf * 16;
                const uint32_t off =
                    SWZ128((uint32_t)((m0 + a_rl) * 128 + (k0 + a_cl) * 2));
                ldsm4(af[mf][0], af[mf][1], af[mf][2], af[mf][3], sA + off);
            }
#pragma unroll
            for (int mf = 0; mf < 4; mf++)
#pragma unroll
                for (int nf = 0; nf < 4; nf++)
                    mma_f16(acc[mf][nf], af[mf], bf[nf]);
        }
    };

    load_chunk(0, 0);
    load_chunk(1, 1);
    for (int kc = 0; kc < NKC; kc++) {
        if (kc + 2 < NKC) {
            load_chunk(kc + 2, (kc + 2) % 3);
            cp_wait<2>();
        } else if (kc + 1 < NKC) {
            cp_wait<1>();
        } else {
            cp_wait<0>();
        }
        __syncthreads();
        compute(kc % 3);
        __syncthreads();
    }

    const int rl = lane >> 2;
    const int cl = (lane & 3) << 1;
#pragma unroll
    for (int mf = 0; mf < 4; mf++) {
        const int m_base = (mtile << 7) + wm * 64 + mf * 16 + rl;
#pragma unroll
        for (int nf = 0; nf < 4; nf++) {
            const int n = (ntile << 7) + wn * 32 + nf * 8 + cl;
            const float b0 = bias[n], b1 = bias[n + 1];
#pragma unroll
            for (int half = 0; half < 2; half++) {
                const int m = m_base + half * 8;
                float v0 = acc[mf][nf][half * 2 + 0] + b0;
                float v1 = acc[mf][nf][half * 2 + 1] + b1;
                if (relu) { v0 = fmaxf(v0, 0.f); v1 = fmaxf(v1, 0.f); }
                if (outF) {
                    float2 f2; f2.x = v0; f2.y = v1;
                    *(float2*)(outF + (size_t)m * DIM + n) = f2;
                } else {
                    *(uint32_t*)(outH + (size_t)m * DIM + n) =
                        (uint32_t)f2h_bits(v0) | ((uint32_t)f2h_bits(v1) << 16);
                }
            }
        }
    }
}

// ---------------------------------------------------------------------------
// Layer-1 fp16 HMMA (K=64): H1 = relu( G3 @ W1g^T + FA_j + FB_i + b1 )
// ---------------------------------------------------------------------------
#define L1_SMEM (2 * 16384 + 128)

__global__ void __launch_bounds__(256, 3)
hmma_l1_kernel(const unsigned short* __restrict__ A,   // G3 fp16 [MBIG, 64]
               const unsigned short* __restrict__ B,   // W1g fp16 [1024, 64]
               const float* __restrict__ bias,
               const float* __restrict__ FA,
               const float* __restrict__ FB,
               unsigned short* __restrict__ outH)
{
    extern __shared__ char smem_raw[];
    const uint32_t sbase = (smem_u32(smem_raw) + 127u) & ~127u;
    const int tid = threadIdx.x;
    const int mtile = blockIdx.y, ntile = blockIdx.x;
    const int lane = tid & 31;
    const int w = tid >> 5;
    const int wm = w >> 2;
    const int wn = w & 3;

#pragma unroll
    for (int it = 0; it < 4; it++) {
        int t = tid + (it << 8);
        int rr = t >> 3, ss = t & 7;
        cp16(sbase + SWZ128((uint32_t)(rr * 128 + ss * 16)),
             A + (size_t)((mtile << 7) + rr) * GEO + ss * 8);
    }
#pragma unroll
    for (int it = 0; it < 4; it++) {
        int t = tid + (it << 8);
        int rr = t >> 3, ss = t & 7;
        cp16(sbase + 16384u + SWZ128((uint32_t)(rr * 128 + ss * 16)),
             B + (size_t)((ntile << 7) + rr) * GEO + ss * 8);
    }
    cp_commit();

    float acc[4][4][4];
#pragma unroll
    for (int mf = 0; mf < 4; mf++)
#pragma unroll
        for (int nf = 0; nf < 4; nf++)
#pragma unroll
            for (int e = 0; e < 4; e++) acc[mf][nf][e] = 0.f;

    const int a_rl = lane & 15;
    const int a_cl = (lane >> 4) << 3;
    const int b_rl = (lane & 7) + ((lane >> 4) << 3);
    const int b_cl = ((lane >> 3) & 1) << 3;

    cp_wait<0>();
    __syncthreads();

    const uint32_t sA = sbase, sB = sbase + 16384u;
#pragma unroll
    for (int ks = 0; ks < 4; ks++) {
        const int k0 = ks * 16;
        uint32_t bf[4][2];
#pragma unroll
        for (int np = 0; np < 2; np++) {
            const int n0 = wn * 32 + np * 16;
            const uint32_t off =
                SWZ128((uint32_t)((n0 + b_rl) * 128 + (k0 + b_cl) * 2));
            uint32_t r0, r1, r2, r3;
            ldsm4(r0, r1, r2, r3, sB + off);
            bf[np * 2][0] = r0; bf[np * 2][1] = r1;
            bf[np * 2 + 1][0] = r2; bf[np * 2 + 1][1] = r3;
        }
        uint32_t af[4][4];
#pragma unroll
        for (int mf = 0; mf < 4; mf++) {
            const int m0 = wm * 64 + mf * 16;
            const uint32_t off =
                SWZ128((uint32_t)((m0 + a_rl) * 128 + (k0 + a_cl) * 2));
            ldsm4(af[mf][0], af[mf][1], af[mf][2], af[mf][3], sA + off);
        }
#pragma unroll
        for (int mf = 0; mf < 4; mf++)
#pragma unroll
            for (int nf = 0; nf < 4; nf++)
                mma_f16(acc[mf][nf], af[mf], bf[nf]);
    }

    const int rl = lane >> 2;
    const int cl = (lane & 3) << 1;
#pragma unroll
    for (int mf = 0; mf < 4; mf++) {
        const int m_base = (mtile << 7) + wm * 64 + mf * 16 + rl;
#pragma unroll
        for (int nf = 0; nf < 4; nf++) {
            const int n = (ntile << 7) + wn * 32 + nf * 8 + cl;
            const float b0 = bias[n], b1 = bias[n + 1];
#pragma unroll
            for (int half = 0; half < 2; half++) {
                const int m = m_base + half * 8;
                const int j = m & (NP - 1);
                const int bi = m >> 7;
                const int bb = bi >> 7;
                const float* aJ = FA + (size_t)((bb << 7) + j) * DIM;
                const float* aI = FB + (size_t)bi * DIM;
                float v0 = acc[mf][nf][half * 2 + 0] + b0 + aJ[n] + aI[n];
                float v1 = acc[mf][nf][half * 2 + 1] + b1 + aJ[n + 1] + aI[n + 1];
                v0 = fmaxf(v0, 0.f); v1 = fmaxf(v1, 0.f);
                *(uint32_t*)(outH + (size_t)m * DIM + n) =
                    (uint32_t)f2h_bits(v0) | ((uint32_t)f2h_bits(v1) << 16);
            }
        }
    }
}

// ---------------------------------------------------------------------------
// Split-K SGEMM for small-M GEMMs
// ---------------------------------------------------------------------------
#define SKM 64
#define SKN 128

__global__ __launch_bounds__(256)
void sgemm_splitk(const float* __restrict__ A, const float* __restrict__ B,
                  float* __restrict__ P, int M, int N, int K, int KSL)
{
    __shared__ float As[16][SKM + 4];
    __shared__ float Bs[16][SKN];

    const int slice = blockIdx.z;
    const int bm = blockIdx.y * SKM;
    const int bn = blockIdx.x * SKN;
    const int tid = threadIdx.x;
    const int arow = tid >> 2, acol = (tid & 3) << 2;
    const int brow = tid >> 5, bcol = (tid & 31) << 2;
    const int tx = tid & 31;
    const int ty = tid >> 5;

    float acc[8][4];
#pragma unroll
    for (int a = 0; a < 8; a++)
#pragma unroll
        for (int b = 0; b < 4; b++) acc[a][b] = 0.f;

    const float* Aptr = A + (size_t)(bm + arow) * K + slice * KSL + acol;
    const float* Bptr = B + (size_t)(slice * KSL + brow) * N + bn + bcol;

    for (int k0 = 0; k0 < KSL; k0 += 16) {
        float4 a0 = *(const float4*)(Aptr + k0);
        float4 b0 = *(const float4*)(Bptr + (size_t)k0 * N);
        float4 b1 = *(const float4*)(Bptr + (size_t)(k0 + 8) * N);
        __syncthreads();
        As[acol + 0][arow] = a0.x; As[acol + 1][arow] = a0.y;
        As[acol + 2][arow] = a0.z; As[acol + 3][arow] = a0.w;
        *(float4*)&Bs[brow][bcol] = b0;
        *(float4*)&Bs[brow + 8][bcol] = b1;
        __syncthreads();
#pragma unroll
        for (int kk = 0; kk < 16; kk++) {
            float ra[8], rb[4];
#pragma unroll
            for (int a = 0; a < 8; a++) ra[a] = As[kk][ty * 8 + a];
#pragma unroll
            for (int b = 0; b < 4; b++) rb[b] = Bs[kk][tx * 4 + b];
#pragma unroll
            for (int a = 0; a < 8; a++)
#pragma unroll
                for (int b = 0; b < 4; b++)
                    acc[a][b] = fmaf(ra[a], rb[b], acc[a][b]);
        }
    }

    float* Pp = P + (size_t)slice * M * N;
#pragma unroll
    for (int a = 0; a < 8; a++) {
        int m = bm + ty * 8 + a;
        float4 v;
        v.x = acc[a][0]; v.y = acc[a][1]; v.z = acc[a][2]; v.w = acc[a][3];
        *(float4*)(Pp + (size_t)m * N + bn + tx * 4) = v;
    }
}

__global__ __launch_bounds__(256)
void skreduce(const float* __restrict__ P, int nsl,
              const float* __restrict__ bias, int relu,
              float* __restrict__ C, int MN, int N)
{
    int idx = blockIdx.x * blockDim.x + threadIdx.x;
    if (idx >= MN) return;
    float s = 0.f;
    for (int sl = 0; sl < nsl; sl++) s += P[(size_t)sl * MN + idx];
    if (bias) s += bias[idx % N];
    if (relu) s = fmaxf(s, 0.f);
    C[idx] = s;
}

// ---------------------------------------------------------------------------
// Weight transpose + fp16 convert:  W[Kd, Nd] -> Wh [Nd, Kd]
// ---------------------------------------------------------------------------
__global__ void wsplit_kernel(const float* __restrict__ W,
                              unsigned short* __restrict__ Wh,
                              int Kd, int Nd)
{
    __shared__ float tile[32][33];
    const int n0 = blockIdx.x * 32, k0 = blockIdx.y * 32;
    const int tx = threadIdx.x, ty = threadIdx.y;   // 32 x 8
#pragma unroll
    for (int i = 0; i < 32; i += 8)
        tile[ty + i][tx] = W[(size_t)(k0 + ty + i) * Nd + n0 + tx];
    __syncthreads();
#pragma unroll
    for (int i = 0; i < 32; i += 8) {
        Wh[(size_t)(n0 + ty + i) * Kd + k0 + tx] = f2h_bits(tile[tx][ty + i]);
    }
}

// ---------------------------------------------------------------------------
// Geo embedding + 3-layer 64-wide MLP (fused) -> fp16 output
// ---------------------------------------------------------------------------
__global__ __launch_bounds__(128)
void geo_kernel(const float* __restrict__ prop,
                const float* __restrict__ w1, const float* __restrict__ b1,
                const float* __restrict__ w2, const float* __restrict__ b2,
                const float* __restrict__ w3, const float* __restrict__ b3,
                unsigned short* __restrict__ G3)
{
    __shared__ float sw1[GEO * GEO], sw2[GEO * GEO], sw3[GEO * GEO];
    __shared__ float sb1[GEO], sb2[GEO], sb3[GEO];
    __shared__ float esm[128 * 65];

    const int tid = threadIdx.x;
    for (int t = tid; t < GEO * GEO; t += blockDim.x) {
        sw1[t] = w1[t]; sw2[t] = w2[t]; sw3[t] = w3[t];
    }
    for (int t = tid; t < GEO; t += blockDim.x) {
        sb1[t] = b1[t]; sb2[t] = b2[t]; sb3[t] = b3[t];
    }
    __syncthreads();

    const int row = blockIdx.x * blockDim.x + tid;
    const int b = row >> 14;
    const int i = (row >> 7) & (NP - 1);
    const int j = row & (NP - 1);

    const float* pi = prop + ((size_t)(b * NP + i)) * 4;
    const float* pj = prop + ((size_t)(b * NP + j)) * 4;
    float wi = pi[2] - pi[0] + 1.f, hi = pi[3] - pi[1] + 1.f;
    float wj = pj[2] - pj[0] + 1.f, hj = pj[3] - pj[1] + 1.f;
    float cxi = 0.5f * (pi[0] + pi[2]), cyi = 0.5f * (pi[1] + pi[3]);
    float cxj = 0.5f * (pj[0] + pj[2]), cyj = 0.5f * (pj[1] + pj[3]);

    float pos[4];
    pos[0] = (cxi - cxj) / wj;
    pos[1] = (cyi - cyj) / hj;
    pos[2] = wi / wj;
    pos[3] = hi / hj;

    const float dm[8] = {1.0f, 2.3713737f, 5.6234133f, 13.335215f,
                         31.622777f, 74.989421f, 177.82794f, 421.69650f};

    float* my = &esm[tid * 65];
#pragma unroll
    for (int p = 0; p < 4; p++) {
        float lp = logf(fmaxf(fabsf(pos[p]), 1e-3f)) * 100.f;
#pragma unroll
        for (int r = 0; r < 8; r++) {
            float arg = lp / dm[r];
            float s, c;
            sincosf(arg, &s, &c);
            my[p * 16 + r] = s;
            my[p * 16 + 8 + r] = c;
        }
    }

    float acc[GEO];
#pragma unroll
    for (int o = 0; o < GEO; o++) acc[o] = sb1[o];
    for (int k = 0; k < GEO; k++) {
        float ek = my[k];
        const float* wr = &sw1[k * GEO];
#pragma unroll
        for (int o = 0; o < GEO; o++) acc[o] = fmaf(ek, wr[o], acc[o]);
    }
#pragma unroll
    for (int o = 0; o < GEO; o++) my[o] = fmaxf(acc[o], 0.f);

#pragma unroll
    for (int o = 0; o < GEO; o++) acc[o] = sb2[o];
    for (int k = 0; k < GEO; k++) {
        float ek = my[k];
        const float* wr = &sw2[k * GEO];
#pragma unroll
        for (int o = 0; o < GEO; o++) acc[o] = fmaf(ek, wr[o], acc[o]);
    }
#pragma unroll
    for (int o = 0; o < GEO; o++) my[o] = fmaxf(acc[o], 0.f);

#pragma unroll
    for (int o = 0; o < GEO; o++) acc[o] = sb3[o];
    for (int k = 0; k < GEO; k++) {
        float ek = my[k];
        const float* wr = &sw3[k * GEO];
#pragma unroll
        for (int o = 0; o < GEO; o++) acc[o] = fmaf(ek, wr[o], acc[o]);
    }
    unsigned short* outp = G3 + (size_t)row * GEO;
#pragma unroll
    for (int o = 0; o < GEO; o++) outp[o] = f2h_bits(acc[o]);
}

// ---------------------------------------------------------------------------
// TopK + concat + heads
// ---------------------------------------------------------------------------
__global__ __launch_bounds__(256)
void topk_kernel(const float* __restrict__ H, float* __restrict__ T)
{
    int idx = blockIdx.x * blockDim.x + threadIdx.x;
    int c = idx & (DIM - 1);
    int bi = idx >> 10;
    const float* p = H + ((size_t)bi * NP) * DIM + c;

    float t[TOPK];
#pragma unroll
    for (int s = 0; s < TOPK; s++) t[s] = -3.4e38f;

    for (int j = 0; j < NP; j++) {
        float v = p[(size_t)j * DIM];
        if (v > t[TOPK - 1]) {
            t[TOPK - 1] = v;
#pragma unroll
            for (int s = TOPK - 1; s > 0; s--) {
                if (t[s] > t[s - 1]) {
                    float tmp = t[s - 1]; t[s - 1] = t[s]; t[s] = tmp;
                }
            }
        }
    }
    float sum = 0.f;
#pragma unroll
    for (int s = 0; s < TOPK; s++) sum += t[s];
    T[idx] = sum * 0.125f;
}

__global__ void cat_kernel(const float* __restrict__ feats,
                           const float* __restrict__ T,
                           float* __restrict__ CAT)
{
    int idx = blockIdx.x * blockDim.x + threadIdx.x;
    int m = idx >> 11;
    int k = idx & 2047;
    float v = (k < DIM) ? feats[(size_t)m * DIM + k]
                        : T[(size_t)m * DIM + (k - DIM)];
    CAT[idx] = v;
}

__global__ __launch_bounds__(128)
void heads_kernel(const float* __restrict__ X,
                  const float* __restrict__ subject,
                  const float* __restrict__ obj,
                  const float* __restrict__ cs_w, const float* __restrict__ cs_b,
                  const float* __restrict__ cso_w, const float* __restrict__ cso_b,
                  float* __restrict__ out)
{
    int row = blockIdx.x;
    int b = row >> 7;
    int tid = threadIdx.x;

    float as = 0.f, ao = 0.f;
    for (int k = tid; k < DIM; k += 128) {
        float xv = X[(size_t)row * DIM + k];
        float sv = subject[(size_t)b * DIM + k];
        float ov = obj[(size_t)b * DIM + k];
        as += xv * cs_w[k] + sv * cs_w[DIM + k];
        ao += xv * cso_w[k] + ov * cso_w[DIM + k];
    }
    __shared__ float rs[128], ro[128];
    rs[tid] = as; ro[tid] = ao;
    __syncthreads();
    for (int s = 64; s > 0; s >>= 1) {
        if (tid < s) { rs[tid] += rs[tid + s]; ro[tid] += ro[tid + s]; }
        __syncthreads();
    }
    if (tid == 0) {
        float s1 = rs[0] + cs_b[0];
        float s2 = ro[0] + cso_b[0];
        out[row * 2 + 0] = 1.f / (1.f + expf(-s1));
        out[row * 2 + 1] = 1.f / (1.f + expf(-s2));
    }
}

// ---------------------------------------------------------------------------
// Launch
// ---------------------------------------------------------------------------
extern "C" void kernel_launch(void* const* d_in, const int* in_sizes, int n_in,
                              void* d_out, int out_size)
{
    const float* feats   = (const float*)d_in[0];
    const float* subject = (const float*)d_in[1];
    const float* obj     = (const float*)d_in[2];
    const float* prop    = (const float*)d_in[3];
    const float* gp_w1 = (const float*)d_in[4];
    const float* gp_b1 = (const float*)d_in[5];
    const float* gp_w2 = (const float*)d_in[6];
    const float* gp_b2 = (const float*)d_in[7];
    const float* gp_w3 = (const float*)d_in[8];
    const float* gp_b3 = (const float*)d_in[9];
    const float* pm_w1 = (const float*)d_in[10];
    const float* pm_b1 = (const float*)d_in[11];
    const float* pm_w2 = (const float*)d_in[12];
    const float* pm_b2 = (const float*)d_in[13];
    const float* pm_w3 = (const float*)d_in[14];
    const float* pm_b3 = (const float*)d_in[15];
    const float* ag_w1 = (const float*)d_in[16];
    const float* ag_b1 = (const float*)d_in[17];
    const float* ag_w2 = (const float*)d_in[18];
    const float* ag_b2 = (const float*)d_in[19];
    const float* ag_w3 = (const float*)d_in[20];
    const float* ag_b3 = (const float*)d_in[21];
    const float* cs_w  = (const float*)d_in[22];
    const float* cs_b  = (const float*)d_in[23];
    const float* cso_w = (const float*)d_in[24];
    const float* cso_b = (const float*)d_in[25];
    float* out = (float*)d_out;

    float *HA, *FA, *FB, *T, *CAT, *SA, *SB, *P;
    unsigned short *G3, *H1, *H2, *W1, *W2, *W3;
    cudaGetSymbolAddress((void**)&HA, g_HA);
    cudaGetSymbolAddress((void**)&FA, g_FA);
    cudaGetSymbolAddress((void**)&FB, g_FB);
    cudaGetSymbolAddress((void**)&T,  g_T);
    cudaGetSymbolAddress((void**)&CAT, g_CAT);
    cudaGetSymbolAddress((void**)&SA, g_SA);
    cudaGetSymbolAddress((void**)&SB, g_SB);
    cudaGetSymbolAddress((void**)&P,  g_P);
    cudaGetSymbolAddress((void**)&G3, g_G3);
    cudaGetSymbolAddress((void**)&H1, g_H1);
    cudaGetSymbolAddress((void**)&H2, g_H2);
    cudaGetSymbolAddress((void**)&W1, g_W1);
    cudaGetSymbolAddress((void**)&W2, g_W2);
    cudaGetSymbolAddress((void**)&W3, g_W3);

    cudaFuncSetAttribute(hmma_kernel,
                         cudaFuncAttributeMaxDynamicSharedMemorySize, HMMA_SMEM);
    cudaFuncSetAttribute(hmma_l1_kernel,
                         cudaFuncAttributeMaxDynamicSharedMemorySize, L1_SMEM);

    dim3 ghm(DIM / 128, MBIG / 128);          // (8, 256)
    dim3 gws(DIM / 32, DIM / 32);
    dim3 gws1(DIM / 32, GEO / 32);
    const int MN = MSMALL * DIM;              // 262144

    // Weight transpose + fp16 convert (tiny)
    wsplit_kernel<<<gws, dim3(32, 8)>>>(pm_w2, W2, DIM, DIM);
    wsplit_kernel<<<gws, dim3(32, 8)>>>(pm_w3, W3, DIM, DIM);
    wsplit_kernel<<<gws1, dim3(32, 8)>>>(pm_w1 + (size_t)2 * DIM * DIM,
                                         W1, GEO, DIM);

    // FA/FB precompute via split-K (K=1024, 8 slices)
    dim3 gsk(DIM / SKN, MSMALL / SKM, 8);     // (8, 4, 8) = 256 CTAs
    sgemm_splitk<<<gsk, 256>>>(feats, pm_w1, P, MSMALL, DIM, DIM, 128);
    skreduce<<<MN / 256, 256>>>(P, 8, nullptr, 0, FA, MN, DIM);
    sgemm_splitk<<<gsk, 256>>>(feats, pm_w1 + (size_t)DIM * DIM, P,
                               MSMALL, DIM, DIM, 128);
    skreduce<<<MN / 256, 256>>>(P, 8, nullptr, 0, FB, MN, DIM);

    // Geo embedding + geo MLP -> fp16
    geo_kernel<<<MBIG / 128, 128>>>(prop, gp_w1, gp_b1, gp_w2, gp_b2,
                                    gp_w3, gp_b3, G3);

    // Pairwise layer 1 (fp16 HMMA, K=64) -> H1 fp16
    hmma_l1_kernel<<<ghm, 256, L1_SMEM>>>(G3, W1, pm_b1, FA, FB, H1);

    // Pairwise layer 2 (fp16 HMMA) -> H2 fp16, relu
    hmma_kernel<<<ghm, 256, HMMA_SMEM>>>(H1, W2, pm_b2, 1, H2, nullptr);
    // Pairwise layer 3 (fp16 HMMA) -> HA fp32, linear
    hmma_kernel<<<ghm, 256, HMMA_SMEM>>>(H2, W3, pm_b3, 0, nullptr, HA);

    // TopK over j, sum/8
    topk_kernel<<<MN / 256, 256>>>(HA, T);

    // Aggregate MLP via split-K
    cat_kernel<<<(MSMALL * 2 * DIM) / 256, 256>>>(feats, T, CAT);
    dim3 gsk16(DIM / SKN, MSMALL / SKM, 16);  // K=2048, 16 slices
    sgemm_splitk<<<gsk16, 256>>>(CAT, ag_w1, P, MSMALL, DIM, 2 * DIM, 128);
    skreduce<<<MN / 256, 256>>>(P, 16, ag_b1, 1, SA, MN, DIM);
    sgemm_splitk<<<gsk, 256>>>(SA, ag_w2, P, MSMALL, DIM, DIM, 128);
    skreduce<<<MN / 256, 256>>>(P, 8, ag_b2, 1, SB, MN, DIM);
    sgemm_splitk<<<gsk, 256>>>(SB, ag_w3, P, MSMALL, DIM, DIM, 128);
    skreduce<<<MN / 256, 256>>>(P, 8, ag_b3, 0, SA, MN, DIM);

    // Heads
    heads_kernel<<<MSMALL, 128>>>(SA, subject, obj, cs_w, cs_b, cso_w, cso_b, out);
}